// round 9
// baseline (speedup 1.0000x reference)
#include <cuda_runtime.h>
#include <cuda_fp16.h>
#include <stdint.h>

#define N_NODES 100000
#define N_EDGES 1600000
#define HID 256
#define SCAN_B 1024

// ---------------- scratch (device globals; no allocation allowed) ----------
__device__ float  g_h[(size_t)N_NODES * HID];
__device__ __half g_hw[(size_t)N_NODES * HID];
__device__ float  g_dinv[N_NODES];
__device__ float  g_self[N_NODES];
__device__ float  g_c1[(size_t)N_NODES * 128];
__device__ float  g_c2[(size_t)N_NODES * 64];
__device__ float  g_c3[(size_t)N_NODES * 32];
__device__ int    g_src32[N_EDGES];
__device__ int    g_dst32[N_EDGES];
__device__ int    g_cnt[N_NODES];
__device__ int    g_ptr[N_NODES + 1];
__device__ int    g_fill[N_NODES];
__device__ int    g_csr_src[N_EDGES];
__device__ float  g_csr_w[N_EDGES];
__device__ int    g_bsum[(N_NODES + SCAN_B - 1) / SCAN_B + 1];
__device__ int    g_is64;

__device__ __forceinline__ uint32_t smem_u32(const void* p) {
    uint32_t a;
    asm("{ .reg .u64 t; cvta.to.shared.u64 t, %1; cvt.u32.u64 %0, t; }" : "=r"(a) : "l"(p));
    return a;
}
__device__ __forceinline__ uint32_t packh2(float lo, float hi) {
    uint32_t o;
    asm("cvt.rn.f16x2.f32 %0, %1, %2;" : "=r"(o) : "f"(hi), "f"(lo));
    return o;
}
__device__ __forceinline__ void cp16(uint32_t dst, const void* src, int valid_bytes) {
    asm volatile("cp.async.ca.shared.global [%0], [%1], 16, %2;"
                 :: "r"(dst), "l"(src), "r"(valid_bytes) : "memory");
}
#define CP_COMMIT() asm volatile("cp.async.commit_group;" ::: "memory")
#define CP_WAIT(n)  asm volatile("cp.async.wait_group %0;" :: "n"(n) : "memory")

// ====== fp16 mma m16n8k16 GEMM: CTA tile 128x256, warp tile 64x64, BK=32 ====
#define ASTR 36
#define BSTR 264
#define ASZ  (128 * ASTR)
#define BSZ  (32 * BSTR)
#define STG  (ASZ + BSZ)
#define MMA_SMEM (2 * STG * 4)

template<bool BIAS, bool RELU, bool HALF_OUT>
__global__ void __launch_bounds__(256) mma_gemm_kernel(
    const float* __restrict__ A, const float* __restrict__ W,
    const float* __restrict__ bias, void* __restrict__ Cv,
    int M, int N, int K)
{
    extern __shared__ float sm[];
    const uint32_t sbase = smem_u32(sm);

    const int tid    = threadIdx.x;
    const int wid    = tid >> 5;
    const int lane   = tid & 31;
    const int gid    = lane >> 2;
    const int t4     = lane & 3;
    const int warp_m = wid >> 2;      // 0..1  (rows: warp_m*64)
    const int warp_n = wid & 3;       // 0..3  (cols: warp_n*64)
    const int row0   = blockIdx.y * 128;
    const int col0   = blockIdx.x * 256;

    float acc[4][8][4];
#pragma unroll
    for (int mt = 0; mt < 4; mt++)
#pragma unroll
        for (int nt = 0; nt < 8; nt++)
#pragma unroll
            for (int q = 0; q < 4; q++) acc[mt][nt][q] = 0.0f;

    const int n_chunks = (K + 31) / 32;

    auto load_chunk = [&](int ch, int st) {
        const int k0 = ch * 32;
        const uint32_t s0 = sbase + (uint32_t)(st * STG) * 4u;
        // A tile: 128 x 32 fp32
#pragma unroll
        for (int t = 0; t < 4; t++) {
            int i  = tid + t * 256;
            int r  = i >> 3;
            int c4 = (i & 7) * 4;
            int gr = row0 + r, gk = k0 + c4;
            int valid = 0;
            if (gr < M) {
                int rem = (K - gk) * 4;
                valid = rem > 16 ? 16 : (rem > 0 ? rem : 0);
            }
            const float* p = valid ? (A + (size_t)gr * K + gk) : A;
            cp16(s0 + (uint32_t)(r * ASTR + c4) * 4u, p, valid);
        }
        // B tile: 32 x 256 fp32
#pragma unroll
        for (int t = 0; t < 8; t++) {
            int i  = tid + t * 256;
            int k  = i >> 6;               // 64 float4 per row
            int n4 = (i & 63) * 4;
            int gk = k0 + k, gn = col0 + n4;
            int valid = (gk < K && gn < N) ? 16 : 0;
            const float* p = valid ? (W + (size_t)gk * N + gn) : W;
            cp16(s0 + (uint32_t)(ASZ + k * BSTR + n4) * 4u, p, valid);
        }
        CP_COMMIT();
    };

    load_chunk(0, 0);

    for (int ch = 0; ch < n_chunks; ch++) {
        if (ch + 1 < n_chunks) {
            load_chunk(ch + 1, (ch + 1) & 1);
            CP_WAIT(1);
        } else {
            CP_WAIT(0);
        }
        __syncthreads();

        const float* As = sm + (ch & 1) * STG;
        const float* Bs = As + ASZ;
#pragma unroll
        for (int ks = 0; ks < 2; ks++) {
            const int kb = ks * 16;
            uint32_t a[4][4], b[8][2];
#pragma unroll
            for (int mt = 0; mt < 4; mt++) {
                int r = warp_m * 64 + mt * 16 + gid;
                float2 lo  = *reinterpret_cast<const float2*>(&As[r * ASTR + kb + 2 * t4]);
                float2 lo8 = *reinterpret_cast<const float2*>(&As[(r + 8) * ASTR + kb + 2 * t4]);
                float2 hi  = *reinterpret_cast<const float2*>(&As[r * ASTR + kb + 8 + 2 * t4]);
                float2 hi8 = *reinterpret_cast<const float2*>(&As[(r + 8) * ASTR + kb + 8 + 2 * t4]);
                a[mt][0] = packh2(lo.x, lo.y);
                a[mt][1] = packh2(lo8.x, lo8.y);
                a[mt][2] = packh2(hi.x, hi.y);
                a[mt][3] = packh2(hi8.x, hi8.y);
            }
#pragma unroll
            for (int nt = 0; nt < 8; nt++) {
                int c = warp_n * 64 + nt * 8 + gid;
                b[nt][0] = packh2(Bs[(kb + 2 * t4) * BSTR + c],
                                  Bs[(kb + 2 * t4 + 1) * BSTR + c]);
                b[nt][1] = packh2(Bs[(kb + 2 * t4 + 8) * BSTR + c],
                                  Bs[(kb + 2 * t4 + 9) * BSTR + c]);
            }
#pragma unroll
            for (int mt = 0; mt < 4; mt++)
#pragma unroll
                for (int nt = 0; nt < 8; nt++) {
                    asm volatile(
                        "mma.sync.aligned.m16n8k16.row.col.f32.f16.f16.f32 "
                        "{%0,%1,%2,%3}, {%4,%5,%6,%7}, {%8,%9}, {%0,%1,%2,%3};"
                        : "+f"(acc[mt][nt][0]), "+f"(acc[mt][nt][1]),
                          "+f"(acc[mt][nt][2]), "+f"(acc[mt][nt][3])
                        : "r"(a[mt][0]), "r"(a[mt][1]), "r"(a[mt][2]), "r"(a[mt][3]),
                          "r"(b[nt][0]), "r"(b[nt][1]));
                }
        }
        __syncthreads();
    }

    // epilogue
#pragma unroll
    for (int mt = 0; mt < 4; mt++) {
#pragma unroll
        for (int half = 0; half < 2; half++) {
            int gr = row0 + warp_m * 64 + mt * 16 + gid + half * 8;
            if (gr >= M) continue;
#pragma unroll
            for (int nt = 0; nt < 8; nt++) {
                int gc = col0 + warp_n * 64 + nt * 8 + t4 * 2;
                if (gc >= N) continue;
                float2 o;
                o.x = acc[mt][nt][half * 2 + 0];
                o.y = acc[mt][nt][half * 2 + 1];
                if (BIAS) {
                    o.x += __ldg(&bias[gc]);
                    o.y += __ldg(&bias[gc + 1]);
                }
                if (RELU) {
                    o.x = fmaxf(o.x, 0.0f);
                    o.y = fmaxf(o.y, 0.0f);
                }
                if (HALF_OUT) {
                    *reinterpret_cast<__half2*>((__half*)Cv + (size_t)gr * N + gc) =
                        __floats2half2_rn(o.x, o.y);
                } else {
                    *reinterpret_cast<float2*>((float*)Cv + (size_t)gr * N + gc) = o;
                }
            }
        }
    }
}

// ---------------- edge dtype detection + conversion -------------------------
__global__ void detect_kernel(const int* __restrict__ e_raw, int n_check) {
    __shared__ int nz;
    if (threadIdx.x == 0) nz = 0;
    __syncthreads();
    for (int i = threadIdx.x; i < n_check; i += blockDim.x)
        if (e_raw[2 * i + 1] != 0) atomicAdd(&nz, 1);
    __syncthreads();
    if (threadIdx.x == 0) g_is64 = (nz == 0) ? 1 : 0;
}

__global__ void convert_count_kernel(const int* __restrict__ e_raw,
                                     int* __restrict__ src32, int* __restrict__ dst32,
                                     int* __restrict__ cnt, int* __restrict__ fill, int E) {
    int i = blockIdx.x * blockDim.x + threadIdx.x;
    if (i < N_NODES) { cnt[i] = 0; fill[i] = 0; }
    if (i >= E) return;
    int s, d;
    if (g_is64) { s = e_raw[2 * i]; d = e_raw[2 * (E + i)]; }
    else        { s = e_raw[i];     d = e_raw[E + i]; }
    src32[i] = s;
    dst32[i] = d;
    atomicAdd(&cnt[d], 1);
}

__global__ void norm_kernel(const int* __restrict__ cnt,
                            float* __restrict__ dinv, float* __restrict__ selfw, int n) {
    int i = blockIdx.x * blockDim.x + threadIdx.x;
    if (i < n) {
        float d = (float)cnt[i] + 1.0f;
        dinv[i]  = rsqrtf(d);
        selfw[i] = 1.0f / d;
    }
}

// ---------------- exclusive scan of cnt -> ptr ------------------------------
__global__ void scan1_kernel(const int* __restrict__ cnt, int* __restrict__ ptr,
                             int* __restrict__ bsum, int n) {
    __shared__ int sh[SCAN_B];
    int b = blockIdx.x;
    int i = b * SCAN_B + threadIdx.x;
    int v = (i < n) ? cnt[i] : 0;
    sh[threadIdx.x] = v;
    __syncthreads();
    for (int off = 1; off < SCAN_B; off <<= 1) {
        int t = (threadIdx.x >= off) ? sh[threadIdx.x - off] : 0;
        __syncthreads();
        sh[threadIdx.x] += t;
        __syncthreads();
    }
    if (i < n) ptr[i] = sh[threadIdx.x] - v;
    if (threadIdx.x == SCAN_B - 1) bsum[b] = sh[SCAN_B - 1];
}

__global__ void scan2_kernel(int* __restrict__ bsum, int nb) {
    __shared__ int sh[256];
    int v = (threadIdx.x < nb) ? bsum[threadIdx.x] : 0;
    sh[threadIdx.x] = v;
    __syncthreads();
    for (int off = 1; off < 256; off <<= 1) {
        int t = (threadIdx.x >= off) ? sh[threadIdx.x - off] : 0;
        __syncthreads();
        sh[threadIdx.x] += t;
        __syncthreads();
    }
    if (threadIdx.x < nb) bsum[threadIdx.x] = sh[threadIdx.x] - v;
}

__global__ void scan3_kernel(int* __restrict__ ptr, const int* __restrict__ bsum,
                             int n, int E) {
    int i = blockIdx.x * SCAN_B + threadIdx.x;
    if (i < n) ptr[i] += bsum[blockIdx.x];
    if (i == n) ptr[n] = E;
}

__global__ void csr_fill_kernel(const int* __restrict__ src, const int* __restrict__ dst,
                                const int* __restrict__ ptr, int* __restrict__ fill,
                                const float* __restrict__ dinv,
                                int* __restrict__ csr_src, float* __restrict__ csr_w, int E) {
    int i = blockIdx.x * blockDim.x + threadIdx.x;
    if (i >= E) return;
    int s = src[i], d = dst[i];
    int pos = atomicAdd(&fill[d], 1);
    int idx = ptr[d] + pos;
    csr_src[idx] = s;
    csr_w[idx] = dinv[s] * dinv[d];
}

// ---------------- SIMT GEMM (small classifier tail) --------------------------
template<int BM, int BN, int BK, int TM, int TN, bool RELU, bool BIAS>
__global__ void gemm_kernel(const float* __restrict__ A, const float* __restrict__ B,
                            const float* __restrict__ bias, float* __restrict__ C,
                            int M, int N, int K)
{
    constexpr int THREADS = (BM / TM) * (BN / TN);
    __shared__ float As[BK][BM];
    __shared__ float Bs[BK][BN];

    const int tid = threadIdx.x;
    const int tx  = tid % (BN / TN);
    const int ty  = tid / (BN / TN);
    const int row0 = blockIdx.y * BM;
    const int col0 = blockIdx.x * BN;

    float acc[TM][TN];
#pragma unroll
    for (int i = 0; i < TM; i++)
#pragma unroll
        for (int j = 0; j < TN; j++) acc[i][j] = 0.0f;

    for (int k0 = 0; k0 < K; k0 += BK) {
#pragma unroll 4
        for (int i = tid; i < BM * BK; i += THREADS) {
            int r = i / BK, c = i % BK;
            int gr = row0 + r, gc = k0 + c;
            As[c][r] = (gr < M && gc < K) ? A[(size_t)gr * K + gc] : 0.0f;
        }
#pragma unroll 4
        for (int i = tid; i < BK * BN; i += THREADS) {
            int r = i / BN, c = i % BN;
            int gk = k0 + r, gc = col0 + c;
            Bs[r][c] = (gk < K && gc < N) ? B[(size_t)gk * N + gc] : 0.0f;
        }
        __syncthreads();
#pragma unroll
        for (int kk = 0; kk < BK; kk++) {
            float a[TM], b[TN];
#pragma unroll
            for (int i = 0; i < TM; i++) a[i] = As[kk][ty * TM + i];
#pragma unroll
            for (int j = 0; j < TN; j++) b[j] = Bs[kk][tx * TN + j];
#pragma unroll
            for (int i = 0; i < TM; i++)
#pragma unroll
                for (int j = 0; j < TN; j++)
                    acc[i][j] = fmaf(a[i], b[j], acc[i][j]);
        }
        __syncthreads();
    }

#pragma unroll
    for (int i = 0; i < TM; i++) {
        int gr = row0 + ty * TM + i;
        if (gr >= M) continue;
#pragma unroll
        for (int j = 0; j < TN; j++) {
            int gc = col0 + tx * TN + j;
            if (gc >= N) continue;
            float v = acc[i][j];
            if (BIAS) v += bias[gc];
            if (RELU) v = fmaxf(v, 0.0f);
            C[(size_t)gr * N + gc] = v;
        }
    }
}

// ---------------- fused aggregation + BN + ReLU + residual ------------------
__global__ void agg_kernel(const int* __restrict__ ptr,
                           const int* __restrict__ csr_src,
                           const float* __restrict__ csr_w,
                           const float* __restrict__ selfw,
                           const __half* __restrict__ hw,
                           const float* __restrict__ cb,
                           const float* __restrict__ gamma,
                           const float* __restrict__ beta,
                           float* __restrict__ h, int N)
{
    int d = blockIdx.x * 8 + (threadIdx.x >> 5);
    if (d >= N) return;
    int lane = threadIdx.x & 31;

    float acc[8];
#pragma unroll
    for (int q = 0; q < 8; q++) acc[q] = 0.0f;

    int beg = __ldg(&ptr[d]);
    int end = __ldg(&ptr[d + 1]);
    int j = beg;
    // unroll by 2: two independent gather slots in flight
    for (; j + 2 <= end; j += 2) {
        int s0 = __ldg(&csr_src[j]);
        int s1 = __ldg(&csr_src[j + 1]);
        float w0 = __ldg(&csr_w[j]);
        float w1 = __ldg(&csr_w[j + 1]);
        uint4 v0 = __ldg(reinterpret_cast<const uint4*>(hw + (size_t)s0 * HID) + lane);
        uint4 v1 = __ldg(reinterpret_cast<const uint4*>(hw + (size_t)s1 * HID) + lane);
        const __half2* p0 = reinterpret_cast<const __half2*>(&v0);
        const __half2* p1 = reinterpret_cast<const __half2*>(&v1);
#pragma unroll
        for (int q = 0; q < 4; q++) {
            float2 f0 = __half22float2(p0[q]);
            float2 f1 = __half22float2(p1[q]);
            acc[2 * q]     = fmaf(f0.x, w0, fmaf(f1.x, w1, acc[2 * q]));
            acc[2 * q + 1] = fmaf(f0.y, w0, fmaf(f1.y, w1, acc[2 * q + 1]));
        }
    }
    for (; j < end; j++) {
        int s = __ldg(&csr_src[j]);
        float w = __ldg(&csr_w[j]);
        uint4 v = __ldg(reinterpret_cast<const uint4*>(hw + (size_t)s * HID) + lane);
        const __half2* p = reinterpret_cast<const __half2*>(&v);
#pragma unroll
        for (int q = 0; q < 4; q++) {
            float2 f = __half22float2(p[q]);
            acc[2 * q]     = fmaf(f.x, w, acc[2 * q]);
            acc[2 * q + 1] = fmaf(f.y, w, acc[2 * q + 1]);
        }
    }

    float sw = __ldg(&selfw[d]);
    uint4 v = __ldg(reinterpret_cast<const uint4*>(hw + (size_t)d * HID) + lane);
    const __half2* p = reinterpret_cast<const __half2*>(&v);
#pragma unroll
    for (int q = 0; q < 4; q++) {
        float2 f = __half22float2(p[q]);
        acc[2 * q]     = fmaf(f.x, sw, acc[2 * q]);
        acc[2 * q + 1] = fmaf(f.y, sw, acc[2 * q + 1]);
    }

    const float4* cb4 = reinterpret_cast<const float4*>(cb);
    const float4* g4  = reinterpret_cast<const float4*>(gamma);
    const float4* bt4 = reinterpret_cast<const float4*>(beta);
    float4* hrow = reinterpret_cast<float4*>(h + (size_t)d * HID);

#pragma unroll
    for (int q2 = 0; q2 < 2; q2++) {
        int c4i = lane * 2 + q2;
        float4 b  = __ldg(&cb4[c4i]);
        float4 g  = __ldg(&g4[c4i]);
        float4 bt = __ldg(&bt4[c4i]);
        float4 hv = hrow[c4i];
        hv.x += fmaxf(fmaf(acc[q2 * 4 + 0] + b.x, g.x, bt.x), 0.0f);
        hv.y += fmaxf(fmaf(acc[q2 * 4 + 1] + b.y, g.y, bt.y), 0.0f);
        hv.z += fmaxf(fmaf(acc[q2 * 4 + 2] + b.z, g.z, bt.z), 0.0f);
        hv.w += fmaxf(fmaf(acc[q2 * 4 + 3] + b.w, g.w, bt.w), 0.0f);
        hrow[c4i] = hv;
    }
}

// ---------------- host launcher ---------------------------------------------
template<bool RELU, bool BIAS>
static void launch_gemm(const float* A, const float* B, const float* bias, float* C,
                        int M, int N, int K) {
    dim3 grid((N + 63) / 64, (M + 127) / 128);
    gemm_kernel<128, 64, 16, 8, 4, RELU, BIAS><<<grid, 256>>>(A, B, bias, C, M, N, K);
}

template<bool BIAS, bool RELU, bool HALF_OUT>
static void launch_mma_gemm(const float* A, const float* W, const float* bias, void* C,
                            int M, int N, int K) {
    cudaFuncSetAttribute(mma_gemm_kernel<BIAS, RELU, HALF_OUT>,
                         cudaFuncAttributeMaxDynamicSharedMemorySize, MMA_SMEM);
    dim3 grid((N + 255) / 256, (M + 127) / 128);
    mma_gemm_kernel<BIAS, RELU, HALF_OUT><<<grid, 256, MMA_SMEM>>>(A, W, bias, C, M, N, K);
}

extern "C" void kernel_launch(void* const* d_in, const int* in_sizes, int n_in,
                              void* d_out, int out_size)
{
    const float* x      = (const float*)d_in[0];
    const int*   e_raw  = (const int*)d_in[1];
    const float* embW   = (const float*)d_in[2];
    const float* embB   = (const float*)d_in[3];
    const float* convW  = (const float*)d_in[4];
    const float* convB  = (const float*)d_in[5];
    const float* gamma  = (const float*)d_in[6];
    const float* beta   = (const float*)d_in[7];
    const float* W0 = (const float*)d_in[8];
    const float* b0 = (const float*)d_in[9];
    const float* W1 = (const float*)d_in[10];
    const float* b1 = (const float*)d_in[11];
    const float* W2 = (const float*)d_in[12];
    const float* b2 = (const float*)d_in[13];
    const float* W3 = (const float*)d_in[14];
    const float* b3 = (const float*)d_in[15];
    float* out = (float*)d_out;

    const int N = N_NODES;
    const int E = in_sizes[1] / 2;

    float *h, *dinv, *selfw, *c1, *c2, *c3, *csr_w;
    __half* hw;
    int *src32, *dst32, *cnt, *ptr, *fill, *csr_src, *bsum;
    cudaGetSymbolAddress((void**)&h,       g_h);
    cudaGetSymbolAddress((void**)&hw,      g_hw);
    cudaGetSymbolAddress((void**)&dinv,    g_dinv);
    cudaGetSymbolAddress((void**)&selfw,   g_self);
    cudaGetSymbolAddress((void**)&c1,      g_c1);
    cudaGetSymbolAddress((void**)&c2,      g_c2);
    cudaGetSymbolAddress((void**)&c3,      g_c3);
    cudaGetSymbolAddress((void**)&src32,   g_src32);
    cudaGetSymbolAddress((void**)&dst32,   g_dst32);
    cudaGetSymbolAddress((void**)&cnt,     g_cnt);
    cudaGetSymbolAddress((void**)&ptr,     g_ptr);
    cudaGetSymbolAddress((void**)&fill,    g_fill);
    cudaGetSymbolAddress((void**)&csr_src, g_csr_src);
    cudaGetSymbolAddress((void**)&csr_w,   g_csr_w);
    cudaGetSymbolAddress((void**)&bsum,    g_bsum);

    int nb = (N + SCAN_B - 1) / SCAN_B;

    // edge prep + CSR build
    detect_kernel<<<1, 256>>>(e_raw, 1024);
    convert_count_kernel<<<(E + 255) / 256, 256>>>(e_raw, src32, dst32, cnt, fill, E);
    norm_kernel<<<(N + 255) / 256, 256>>>(cnt, dinv, selfw, N);
    scan1_kernel<<<nb, SCAN_B>>>(cnt, ptr, bsum, N);
    scan2_kernel<<<1, 256>>>(bsum, nb);

    // embed GEMM (independent of CSR build)
    launch_mma_gemm<true, false, false>(x, embW, embB, h, N, HID, 500);

    scan3_kernel<<<nb + 1, SCAN_B>>>(ptr, bsum, N, E);
    csr_fill_kernel<<<(E + 255) / 256, 256>>>(src32, dst32, ptr, fill, dinv, csr_src, csr_w, E);

    // GCN layers: fp16 tensor GEMM (fp16 out) + fused aggregation/epilogue
    const int agg_blocks = (N + 7) / 8;
    for (int l = 0; l < 3; l++) {
        const float* Wl  = convW + (size_t)l * HID * HID;
        const float* cbl = convB + (size_t)l * HID;
        const float* gl  = gamma + (size_t)l * HID;
        const float* btl = beta  + (size_t)l * HID;

        launch_mma_gemm<false, false, true>(h, Wl, nullptr, hw, N, HID, HID);
        agg_kernel<<<agg_blocks, 256>>>(ptr, csr_src, csr_w, selfw, hw, cbl, gl, btl, h, N);
    }

    // classifier MLP
    launch_mma_gemm<true, true, false>(h,  W0, b0, c1, N, 128, 256);
    launch_mma_gemm<true, true, false>(c1, W1, b1, c2, N, 64,  128);
    launch_gemm<true,  true>(c2, W2, b2, c3,  N, 32, 64);
    launch_gemm<false, true>(c3, W3, b3, out, N, 40, 32);
}

// round 10
// speedup vs baseline: 1.3010x; 1.3010x over previous
#include <cuda_runtime.h>
#include <cuda_fp16.h>
#include <stdint.h>

#define N_NODES 100000
#define N_EDGES 1600000
#define HID 256
#define SCAN_B 1024

// ---------------- scratch (device globals; no allocation allowed) ----------
__device__ float  g_h[(size_t)N_NODES * HID];
__device__ __half g_hw[(size_t)N_NODES * HID];
__device__ float  g_dinv[N_NODES];
__device__ float  g_self[N_NODES];
__device__ float  g_c1[(size_t)N_NODES * 128];
__device__ float  g_c2[(size_t)N_NODES * 64];
__device__ float  g_c3[(size_t)N_NODES * 32];
__device__ int    g_src32[N_EDGES];
__device__ int    g_dst32[N_EDGES];
__device__ int    g_cnt[N_NODES];
__device__ int    g_ptr[N_NODES + 1];
__device__ int    g_fill[N_NODES];
__device__ int    g_csr_src[N_EDGES];
__device__ int    g_bsum[(N_NODES + SCAN_B - 1) / SCAN_B + 1];
__device__ int    g_is64;

__device__ __forceinline__ uint32_t smem_u32(const void* p) {
    uint32_t a;
    asm("{ .reg .u64 t; cvta.to.shared.u64 t, %1; cvt.u32.u64 %0, t; }" : "=r"(a) : "l"(p));
    return a;
}
__device__ __forceinline__ uint32_t packh2(float lo, float hi) {
    uint32_t o;
    asm("cvt.rn.f16x2.f32 %0, %1, %2;" : "=r"(o) : "f"(hi), "f"(lo));
    return o;
}

// ====== fp16 mma m16n8k16 GEMM with ldmatrix fragments =======================
// CTA tile 128x128, BK=32, 8 warps (2 M x 4 N), warp tile 64x32.
// Smem tiles stored as fp16 (converted during global->smem), 2 stages.
#define ASTRH 40                      // halves per A row (32 data + 8 pad)
#define BSTRH 136                     // halves per B row (128 data + 8 pad)
#define A_BYTES (128 * ASTRH * 2)     // 10240
#define B_BYTES (32 * BSTRH * 2)      // 8704
#define STG_BYTES (A_BYTES + B_BYTES) // 18944
#define MMA_SMEM (2 * STG_BYTES)      // 37888

template<bool BIAS, bool RELU, bool HALF_OUT>
__global__ void __launch_bounds__(256, 2) mma_gemm_kernel(
    const float* __restrict__ A, const float* __restrict__ W,
    const float* __restrict__ bias, void* __restrict__ Cv,
    int M, int N, int K)
{
    extern __shared__ char smc[];
    const uint32_t sbase = smem_u32(smc);

    const int tid    = threadIdx.x;
    const int wid    = tid >> 5;
    const int lane   = tid & 31;
    const int gid    = lane >> 2;
    const int t4     = lane & 3;
    const int warp_m = wid >> 2;
    const int warp_n = wid & 3;
    const int row0   = blockIdx.y * 128;
    const int col0   = blockIdx.x * 128;

    float acc[4][4][4];
#pragma unroll
    for (int mt = 0; mt < 4; mt++)
#pragma unroll
        for (int nt = 0; nt < 4; nt++)
#pragma unroll
            for (int q = 0; q < 4; q++) acc[mt][nt][q] = 0.0f;

    const int n_chunks = (K + 31) / 32;
    float4 pa[4], pb[4];

    auto ldg_chunk = [&](int ch) {
        const int k0 = ch * 32;
#pragma unroll
        for (int t = 0; t < 4; t++) {          // A: 128 x 32 fp32
            int i  = tid + t * 256;
            int r  = i >> 3, c4 = (i & 7) * 4;
            int gr = row0 + r, gk = k0 + c4;
            if (gr < M && gk + 4 <= K)
                pa[t] = *reinterpret_cast<const float4*>(A + (size_t)gr * K + gk);
            else
                pa[t] = make_float4(0.f, 0.f, 0.f, 0.f);
        }
#pragma unroll
        for (int t = 0; t < 4; t++) {          // B: 32 x 128 fp32
            int i  = tid + t * 256;
            int r  = i >> 5, c4 = (i & 31) * 4;
            int gk = k0 + r, gn = col0 + c4;
            if (gk < K && gn + 4 <= N)
                pb[t] = *reinterpret_cast<const float4*>(W + (size_t)gk * N + gn);
            else
                pb[t] = make_float4(0.f, 0.f, 0.f, 0.f);
        }
    };

    auto sts_chunk = [&](int st) {
        const uint32_t s0 = sbase + (uint32_t)st * STG_BYTES;
#pragma unroll
        for (int t = 0; t < 4; t++) {
            int i = tid + t * 256;
            int r = i >> 3, c4 = i & 7;
            uint2 v = make_uint2(packh2(pa[t].x, pa[t].y), packh2(pa[t].z, pa[t].w));
            *reinterpret_cast<uint2*>(smc + (st * STG_BYTES) + r * (ASTRH * 2) + c4 * 8) = v;
        }
#pragma unroll
        for (int t = 0; t < 4; t++) {
            int i = tid + t * 256;
            int r = i >> 5, c4 = i & 31;
            uint2 v = make_uint2(packh2(pb[t].x, pb[t].y), packh2(pb[t].z, pb[t].w));
            *reinterpret_cast<uint2*>(smc + (st * STG_BYTES) + A_BYTES + r * (BSTRH * 2) + c4 * 8) = v;
        }
        (void)s0;
    };

    auto compute = [&](int st) {
        const uint32_t a_base = sbase + (uint32_t)st * STG_BYTES;
        const uint32_t b_base = a_base + A_BYTES;
#pragma unroll
        for (int ks = 0; ks < 2; ks++) {
            const int kb = ks * 16;
            uint32_t a[4][4], b[4][2];
#pragma unroll
            for (int mt = 0; mt < 4; mt++) {
                uint32_t addr = a_base +
                    (uint32_t)((warp_m * 64 + mt * 16 + (lane & 15)) * ASTRH +
                               kb + ((lane >> 4) << 3)) * 2u;
                asm volatile("ldmatrix.sync.aligned.m8n8.x4.shared.b16 {%0,%1,%2,%3}, [%4];"
                             : "=r"(a[mt][0]), "=r"(a[mt][1]), "=r"(a[mt][2]), "=r"(a[mt][3])
                             : "r"(addr));
            }
#pragma unroll
            for (int nt2 = 0; nt2 < 2; nt2++) {
                uint32_t addr = b_base +
                    (uint32_t)((kb + (lane & 15)) * BSTRH +
                               warp_n * 32 + nt2 * 16 + ((lane >> 4) << 3)) * 2u;
                asm volatile("ldmatrix.sync.aligned.m8n8.x4.trans.shared.b16 {%0,%1,%2,%3}, [%4];"
                             : "=r"(b[nt2 * 2][0]), "=r"(b[nt2 * 2][1]),
                               "=r"(b[nt2 * 2 + 1][0]), "=r"(b[nt2 * 2 + 1][1])
                             : "r"(addr));
            }
#pragma unroll
            for (int mt = 0; mt < 4; mt++)
#pragma unroll
                for (int nt = 0; nt < 4; nt++) {
                    asm volatile(
                        "mma.sync.aligned.m16n8k16.row.col.f32.f16.f16.f32 "
                        "{%0,%1,%2,%3}, {%4,%5,%6,%7}, {%8,%9}, {%0,%1,%2,%3};"
                        : "+f"(acc[mt][nt][0]), "+f"(acc[mt][nt][1]),
                          "+f"(acc[mt][nt][2]), "+f"(acc[mt][nt][3])
                        : "r"(a[mt][0]), "r"(a[mt][1]), "r"(a[mt][2]), "r"(a[mt][3]),
                          "r"(b[nt][0]), "r"(b[nt][1]));
                }
        }
    };

    ldg_chunk(0);
    sts_chunk(0);
    __syncthreads();

    for (int ch = 0; ch < n_chunks; ch++) {
        bool next = (ch + 1 < n_chunks);
        if (next) ldg_chunk(ch + 1);
        compute(ch & 1);
        if (next) {
            sts_chunk((ch + 1) & 1);
            __syncthreads();
        }
    }

    // epilogue
#pragma unroll
    for (int mt = 0; mt < 4; mt++) {
#pragma unroll
        for (int half = 0; half < 2; half++) {
            int gr = row0 + warp_m * 64 + mt * 16 + gid + half * 8;
            if (gr >= M) continue;
#pragma unroll
            for (int nt = 0; nt < 4; nt++) {
                int gc = col0 + warp_n * 32 + nt * 8 + t4 * 2;
                if (gc >= N) continue;
                float2 o;
                o.x = acc[mt][nt][half * 2 + 0];
                o.y = acc[mt][nt][half * 2 + 1];
                if (BIAS) {
                    o.x += __ldg(&bias[gc]);
                    o.y += __ldg(&bias[gc + 1]);
                }
                if (RELU) {
                    o.x = fmaxf(o.x, 0.0f);
                    o.y = fmaxf(o.y, 0.0f);
                }
                if (HALF_OUT) {
                    *reinterpret_cast<__half2*>((__half*)Cv + (size_t)gr * N + gc) =
                        __floats2half2_rn(o.x, o.y);
                } else {
                    *reinterpret_cast<float2*>((float*)Cv + (size_t)gr * N + gc) = o;
                }
            }
        }
    }
}

// ---------------- edge dtype detection + conversion -------------------------
__global__ void detect_kernel(const int* __restrict__ e_raw, int n_check) {
    __shared__ int nz;
    if (threadIdx.x == 0) nz = 0;
    __syncthreads();
    for (int i = threadIdx.x; i < n_check; i += blockDim.x)
        if (e_raw[2 * i + 1] != 0) atomicAdd(&nz, 1);
    __syncthreads();
    if (threadIdx.x == 0) g_is64 = (nz == 0) ? 1 : 0;
}

__global__ void convert_count_kernel(const int* __restrict__ e_raw,
                                     int* __restrict__ src32, int* __restrict__ dst32,
                                     int* __restrict__ cnt, int* __restrict__ fill, int E) {
    int i = blockIdx.x * blockDim.x + threadIdx.x;
    if (i < N_NODES) { cnt[i] = 0; fill[i] = 0; }
    if (i >= E) return;
    int s, d;
    if (g_is64) { s = e_raw[2 * i]; d = e_raw[2 * (E + i)]; }
    else        { s = e_raw[i];     d = e_raw[E + i]; }
    src32[i] = s;
    dst32[i] = d;
    atomicAdd(&cnt[d], 1);
}

__global__ void norm_kernel(const int* __restrict__ cnt,
                            float* __restrict__ dinv, float* __restrict__ selfw, int n) {
    int i = blockIdx.x * blockDim.x + threadIdx.x;
    if (i < n) {
        float d = (float)cnt[i] + 1.0f;
        dinv[i]  = rsqrtf(d);
        selfw[i] = 1.0f / d;
    }
}

// ---------------- exclusive scan of cnt -> ptr ------------------------------
__global__ void scan1_kernel(const int* __restrict__ cnt, int* __restrict__ ptr,
                             int* __restrict__ bsum, int n) {
    __shared__ int sh[SCAN_B];
    int b = blockIdx.x;
    int i = b * SCAN_B + threadIdx.x;
    int v = (i < n) ? cnt[i] : 0;
    sh[threadIdx.x] = v;
    __syncthreads();
    for (int off = 1; off < SCAN_B; off <<= 1) {
        int t = (threadIdx.x >= off) ? sh[threadIdx.x - off] : 0;
        __syncthreads();
        sh[threadIdx.x] += t;
        __syncthreads();
    }
    if (i < n) ptr[i] = sh[threadIdx.x] - v;
    if (threadIdx.x == SCAN_B - 1) bsum[b] = sh[SCAN_B - 1];
}

__global__ void scan2_kernel(int* __restrict__ bsum, int nb) {
    __shared__ int sh[256];
    int v = (threadIdx.x < nb) ? bsum[threadIdx.x] : 0;
    sh[threadIdx.x] = v;
    __syncthreads();
    for (int off = 1; off < 256; off <<= 1) {
        int t = (threadIdx.x >= off) ? sh[threadIdx.x - off] : 0;
        __syncthreads();
        sh[threadIdx.x] += t;
        __syncthreads();
    }
    if (threadIdx.x < nb) bsum[threadIdx.x] = sh[threadIdx.x] - v;
}

__global__ void scan3_kernel(int* __restrict__ ptr, const int* __restrict__ bsum,
                             int n, int E) {
    int i = blockIdx.x * SCAN_B + threadIdx.x;
    if (i < n) ptr[i] += bsum[blockIdx.x];
    if (i == n) ptr[n] = E;
}

__global__ void csr_fill_kernel(const int* __restrict__ src, const int* __restrict__ dst,
                                const int* __restrict__ ptr, int* __restrict__ fill,
                                int* __restrict__ csr_src, int E) {
    int i = blockIdx.x * blockDim.x + threadIdx.x;
    if (i >= E) return;
    int s = src[i], d = dst[i];
    int pos = atomicAdd(&fill[d], 1);
    csr_src[ptr[d] + pos] = s;
}

// ---------------- SIMT GEMM (small classifier tail) --------------------------
template<int BM, int BN, int BK, int TM, int TN, bool RELU, bool BIAS>
__global__ void gemm_kernel(const float* __restrict__ A, const float* __restrict__ B,
                            const float* __restrict__ bias, float* __restrict__ C,
                            int M, int N, int K)
{
    constexpr int THREADS = (BM / TM) * (BN / TN);
    __shared__ float As[BK][BM];
    __shared__ float Bs[BK][BN];

    const int tid = threadIdx.x;
    const int tx  = tid % (BN / TN);
    const int ty  = tid / (BN / TN);
    const int row0 = blockIdx.y * BM;
    const int col0 = blockIdx.x * BN;

    float acc[TM][TN];
#pragma unroll
    for (int i = 0; i < TM; i++)
#pragma unroll
        for (int j = 0; j < TN; j++) acc[i][j] = 0.0f;

    for (int k0 = 0; k0 < K; k0 += BK) {
#pragma unroll 4
        for (int i = tid; i < BM * BK; i += THREADS) {
            int r = i / BK, c = i % BK;
            int gr = row0 + r, gc = k0 + c;
            As[c][r] = (gr < M && gc < K) ? A[(size_t)gr * K + gc] : 0.0f;
        }
#pragma unroll 4
        for (int i = tid; i < BK * BN; i += THREADS) {
            int r = i / BN, c = i % BN;
            int gk = k0 + r, gc = col0 + c;
            Bs[r][c] = (gk < K && gc < N) ? B[(size_t)gk * N + gc] : 0.0f;
        }
        __syncthreads();
#pragma unroll
        for (int kk = 0; kk < BK; kk++) {
            float a[TM], b[TN];
#pragma unroll
            for (int i = 0; i < TM; i++) a[i] = As[kk][ty * TM + i];
#pragma unroll
            for (int j = 0; j < TN; j++) b[j] = Bs[kk][tx * TN + j];
#pragma unroll
            for (int i = 0; i < TM; i++)
#pragma unroll
                for (int j = 0; j < TN; j++)
                    acc[i][j] = fmaf(a[i], b[j], acc[i][j]);
        }
        __syncthreads();
    }

#pragma unroll
    for (int i = 0; i < TM; i++) {
        int gr = row0 + ty * TM + i;
        if (gr >= M) continue;
#pragma unroll
        for (int j = 0; j < TN; j++) {
            int gc = col0 + tx * TN + j;
            if (gc >= N) continue;
            float v = acc[i][j];
            if (BIAS) v += bias[gc];
            if (RELU) v = fmaxf(v, 0.0f);
            C[(size_t)gr * N + gc] = v;
        }
    }
}

// ---------------- fused aggregation + BN + ReLU + residual ------------------
__global__ void agg_kernel(const int* __restrict__ ptr,
                           const int* __restrict__ csr_src,
                           const float* __restrict__ dinv,
                           const float* __restrict__ selfw,
                           const __half* __restrict__ hw,
                           const float* __restrict__ cb,
                           const float* __restrict__ gamma,
                           const float* __restrict__ beta,
                           float* __restrict__ h, int N)
{
    int d = blockIdx.x * 8 + (threadIdx.x >> 5);
    if (d >= N) return;
    int lane = threadIdx.x & 31;

    float acc[8];
#pragma unroll
    for (int q = 0; q < 8; q++) acc[q] = 0.0f;

    float dv_d = __ldg(&dinv[d]);
    int beg = __ldg(&ptr[d]);
    int end = __ldg(&ptr[d + 1]);
    int j = beg;
    for (; j + 2 <= end; j += 2) {
        int s0 = __ldg(&csr_src[j]);
        int s1 = __ldg(&csr_src[j + 1]);
        float w0 = __ldg(&dinv[s0]) * dv_d;
        float w1 = __ldg(&dinv[s1]) * dv_d;
        uint4 v0 = __ldg(reinterpret_cast<const uint4*>(hw + (size_t)s0 * HID) + lane);
        uint4 v1 = __ldg(reinterpret_cast<const uint4*>(hw + (size_t)s1 * HID) + lane);
        const __half2* p0 = reinterpret_cast<const __half2*>(&v0);
        const __half2* p1 = reinterpret_cast<const __half2*>(&v1);
#pragma unroll
        for (int q = 0; q < 4; q++) {
            float2 f0 = __half22float2(p0[q]);
            float2 f1 = __half22float2(p1[q]);
            acc[2 * q]     = fmaf(f0.x, w0, fmaf(f1.x, w1, acc[2 * q]));
            acc[2 * q + 1] = fmaf(f0.y, w0, fmaf(f1.y, w1, acc[2 * q + 1]));
        }
    }
    for (; j < end; j++) {
        int s = __ldg(&csr_src[j]);
        float w = __ldg(&dinv[s]) * dv_d;
        uint4 v = __ldg(reinterpret_cast<const uint4*>(hw + (size_t)s * HID) + lane);
        const __half2* p = reinterpret_cast<const __half2*>(&v);
#pragma unroll
        for (int q = 0; q < 4; q++) {
            float2 f = __half22float2(p[q]);
            acc[2 * q]     = fmaf(f.x, w, acc[2 * q]);
            acc[2 * q + 1] = fmaf(f.y, w, acc[2 * q + 1]);
        }
    }

    float sw = __ldg(&selfw[d]);
    uint4 v = __ldg(reinterpret_cast<const uint4*>(hw + (size_t)d * HID) + lane);
    const __half2* p = reinterpret_cast<const __half2*>(&v);
#pragma unroll
    for (int q = 0; q < 4; q++) {
        float2 f = __half22float2(p[q]);
        acc[2 * q]     = fmaf(f.x, sw, acc[2 * q]);
        acc[2 * q + 1] = fmaf(f.y, sw, acc[2 * q + 1]);
    }

    const float4* cb4 = reinterpret_cast<const float4*>(cb);
    const float4* g4  = reinterpret_cast<const float4*>(gamma);
    const float4* bt4 = reinterpret_cast<const float4*>(beta);
    float4* hrow = reinterpret_cast<float4*>(h + (size_t)d * HID);

#pragma unroll
    for (int q2 = 0; q2 < 2; q2++) {
        int c4i = lane * 2 + q2;
        float4 b  = __ldg(&cb4[c4i]);
        float4 g  = __ldg(&g4[c4i]);
        float4 bt = __ldg(&bt4[c4i]);
        float4 hv = hrow[c4i];
        hv.x += fmaxf(fmaf(acc[q2 * 4 + 0] + b.x, g.x, bt.x), 0.0f);
        hv.y += fmaxf(fmaf(acc[q2 * 4 + 1] + b.y, g.y, bt.y), 0.0f);
        hv.z += fmaxf(fmaf(acc[q2 * 4 + 2] + b.z, g.z, bt.z), 0.0f);
        hv.w += fmaxf(fmaf(acc[q2 * 4 + 3] + b.w, g.w, bt.w), 0.0f);
        hrow[c4i] = hv;
    }
}

// ---------------- host launcher ---------------------------------------------
template<bool RELU, bool BIAS>
static void launch_gemm(const float* A, const float* B, const float* bias, float* C,
                        int M, int N, int K) {
    dim3 grid((N + 63) / 64, (M + 127) / 128);
    gemm_kernel<128, 64, 16, 8, 4, RELU, BIAS><<<grid, 256>>>(A, B, bias, C, M, N, K);
}

template<bool BIAS, bool RELU, bool HALF_OUT>
static void launch_mma_gemm(const float* A, const float* W, const float* bias, void* C,
                            int M, int N, int K) {
    cudaFuncSetAttribute(mma_gemm_kernel<BIAS, RELU, HALF_OUT>,
                         cudaFuncAttributeMaxDynamicSharedMemorySize, MMA_SMEM);
    dim3 grid((N + 127) / 128, (M + 127) / 128);
    mma_gemm_kernel<BIAS, RELU, HALF_OUT><<<grid, 256, MMA_SMEM>>>(A, W, bias, C, M, N, K);
}

extern "C" void kernel_launch(void* const* d_in, const int* in_sizes, int n_in,
                              void* d_out, int out_size)
{
    const float* x      = (const float*)d_in[0];
    const int*   e_raw  = (const int*)d_in[1];
    const float* embW   = (const float*)d_in[2];
    const float* embB   = (const float*)d_in[3];
    const float* convW  = (const float*)d_in[4];
    const float* convB  = (const float*)d_in[5];
    const float* gamma  = (const float*)d_in[6];
    const float* beta   = (const float*)d_in[7];
    const float* W0 = (const float*)d_in[8];
    const float* b0 = (const float*)d_in[9];
    const float* W1 = (const float*)d_in[10];
    const float* b1 = (const float*)d_in[11];
    const float* W2 = (const float*)d_in[12];
    const float* b2 = (const float*)d_in[13];
    const float* W3 = (const float*)d_in[14];
    const float* b3 = (const float*)d_in[15];
    float* out = (float*)d_out;

    const int N = N_NODES;
    const int E = in_sizes[1] / 2;

    float *h, *dinv, *selfw, *c1, *c2, *c3;
    __half* hw;
    int *src32, *dst32, *cnt, *ptr, *fill, *csr_src, *bsum;
    cudaGetSymbolAddress((void**)&h,       g_h);
    cudaGetSymbolAddress((void**)&hw,      g_hw);
    cudaGetSymbolAddress((void**)&dinv,    g_dinv);
    cudaGetSymbolAddress((void**)&selfw,   g_self);
    cudaGetSymbolAddress((void**)&c1,      g_c1);
    cudaGetSymbolAddress((void**)&c2,      g_c2);
    cudaGetSymbolAddress((void**)&c3,      g_c3);
    cudaGetSymbolAddress((void**)&src32,   g_src32);
    cudaGetSymbolAddress((void**)&dst32,   g_dst32);
    cudaGetSymbolAddress((void**)&cnt,     g_cnt);
    cudaGetSymbolAddress((void**)&ptr,     g_ptr);
    cudaGetSymbolAddress((void**)&fill,    g_fill);
    cudaGetSymbolAddress((void**)&csr_src, g_csr_src);
    cudaGetSymbolAddress((void**)&bsum,    g_bsum);

    int nb = (N + SCAN_B - 1) / SCAN_B;

    // edge prep + CSR build
    detect_kernel<<<1, 256>>>(e_raw, 1024);
    convert_count_kernel<<<(E + 255) / 256, 256>>>(e_raw, src32, dst32, cnt, fill, E);
    norm_kernel<<<(N + 255) / 256, 256>>>(cnt, dinv, selfw, N);
    scan1_kernel<<<nb, SCAN_B>>>(cnt, ptr, bsum, N);
    scan2_kernel<<<1, 256>>>(bsum, nb);

    // embed GEMM (independent of CSR build)
    launch_mma_gemm<true, false, false>(x, embW, embB, h, N, HID, 500);

    scan3_kernel<<<nb + 1, SCAN_B>>>(ptr, bsum, N, E);
    csr_fill_kernel<<<(E + 255) / 256, 256>>>(src32, dst32, ptr, fill, csr_src, E);

    // GCN layers
    const int agg_blocks = (N + 7) / 8;
    for (int l = 0; l < 3; l++) {
        const float* Wl  = convW + (size_t)l * HID * HID;
        const float* cbl = convB + (size_t)l * HID;
        const float* gl  = gamma + (size_t)l * HID;
        const float* btl = beta  + (size_t)l * HID;

        launch_mma_gemm<false, false, true>(h, Wl, nullptr, hw, N, HID, HID);
        agg_kernel<<<agg_blocks, 256>>>(ptr, csr_src, dinv, selfw, hw, cbl, gl, btl, h, N);
    }

    // classifier MLP
    launch_mma_gemm<true, true, false>(h,  W0, b0, c1, N, 128, 256);
    launch_mma_gemm<true, true, false>(c1, W1, b1, c2, N, 64,  128);
    launch_gemm<true,  true>(c2, W2, b2, c3,  N, 32, 64);
    launch_gemm<false, true>(c3, W3, b3, out, N, 40, 32);
}

// round 11
// speedup vs baseline: 1.3025x; 1.0012x over previous
#include <cuda_runtime.h>
#include <cuda_fp16.h>
#include <stdint.h>

#define N_NODES 100000
#define N_EDGES 1600000
#define HID 256
#define SCAN_B 1024

// ---------------- scratch (device globals; no allocation allowed) ----------
__device__ float  g_h[(size_t)N_NODES * HID];
__device__ __half g_hw[(size_t)N_NODES * HID];
__device__ float  g_dinv[N_NODES];
__device__ float  g_self[N_NODES];
__device__ float  g_c1[(size_t)N_NODES * 128];
__device__ float  g_c2[(size_t)N_NODES * 64];
__device__ int    g_src32[N_EDGES];
__device__ int    g_dst32[N_EDGES];
__device__ int    g_cnt[N_NODES];
__device__ int    g_ptr[N_NODES + 1];
__device__ int    g_fill[N_NODES];
__device__ int    g_csr_src[N_EDGES];
__device__ int    g_bsum[(N_NODES + SCAN_B - 1) / SCAN_B + 1];
__device__ int    g_is64;

__device__ __forceinline__ uint32_t smem_u32(const void* p) {
    uint32_t a;
    asm("{ .reg .u64 t; cvta.to.shared.u64 t, %1; cvt.u32.u64 %0, t; }" : "=r"(a) : "l"(p));
    return a;
}
__device__ __forceinline__ uint32_t packh2(float lo, float hi) {
    uint32_t o;
    asm("cvt.rn.f16x2.f32 %0, %1, %2;" : "=r"(o) : "f"(hi), "f"(lo));
    return o;
}

// ====== fp16 mma m16n8k16 GEMM with ldmatrix fragments =======================
#define ASTRH 40
#define BSTRH 136
#define A_BYTES (128 * ASTRH * 2)
#define B_BYTES (32 * BSTRH * 2)
#define STG_BYTES (A_BYTES + B_BYTES)
#define MMA_SMEM (2 * STG_BYTES)

template<bool BIAS, bool RELU, bool HALF_OUT>
__global__ void __launch_bounds__(256, 2) mma_gemm_kernel(
    const float* __restrict__ A, const float* __restrict__ W,
    const float* __restrict__ bias, void* __restrict__ Cv,
    int M, int N, int K)
{
    extern __shared__ char smc[];
    const uint32_t sbase = smem_u32(smc);

    const int tid    = threadIdx.x;
    const int wid    = tid >> 5;
    const int lane   = tid & 31;
    const int gid    = lane >> 2;
    const int t4     = lane & 3;
    const int warp_m = wid >> 2;
    const int warp_n = wid & 3;
    const int row0   = blockIdx.y * 128;
    const int col0   = blockIdx.x * 128;

    float acc[4][4][4];
#pragma unroll
    for (int mt = 0; mt < 4; mt++)
#pragma unroll
        for (int nt = 0; nt < 4; nt++)
#pragma unroll
            for (int q = 0; q < 4; q++) acc[mt][nt][q] = 0.0f;

    const int n_chunks = (K + 31) / 32;
    float4 pa[4], pb[4];

    auto ldg_chunk = [&](int ch) {
        const int k0 = ch * 32;
#pragma unroll
        for (int t = 0; t < 4; t++) {
            int i  = tid + t * 256;
            int r  = i >> 3, c4 = (i & 7) * 4;
            int gr = row0 + r, gk = k0 + c4;
            if (gr < M && gk + 4 <= K)
                pa[t] = *reinterpret_cast<const float4*>(A + (size_t)gr * K + gk);
            else
                pa[t] = make_float4(0.f, 0.f, 0.f, 0.f);
        }
#pragma unroll
        for (int t = 0; t < 4; t++) {
            int i  = tid + t * 256;
            int r  = i >> 5, c4 = (i & 31) * 4;
            int gk = k0 + r, gn = col0 + c4;
            if (gk < K && gn + 4 <= N)
                pb[t] = *reinterpret_cast<const float4*>(W + (size_t)gk * N + gn);
            else
                pb[t] = make_float4(0.f, 0.f, 0.f, 0.f);
        }
    };

    auto sts_chunk = [&](int st) {
#pragma unroll
        for (int t = 0; t < 4; t++) {
            int i = tid + t * 256;
            int r = i >> 3, c4 = i & 7;
            uint2 v = make_uint2(packh2(pa[t].x, pa[t].y), packh2(pa[t].z, pa[t].w));
            *reinterpret_cast<uint2*>(smc + (st * STG_BYTES) + r * (ASTRH * 2) + c4 * 8) = v;
        }
#pragma unroll
        for (int t = 0; t < 4; t++) {
            int i = tid + t * 256;
            int r = i >> 5, c4 = i & 31;
            uint2 v = make_uint2(packh2(pb[t].x, pb[t].y), packh2(pb[t].z, pb[t].w));
            *reinterpret_cast<uint2*>(smc + (st * STG_BYTES) + A_BYTES + r * (BSTRH * 2) + c4 * 8) = v;
        }
    };

    auto compute = [&](int st) {
        const uint32_t a_base = sbase + (uint32_t)st * STG_BYTES;
        const uint32_t b_base = a_base + A_BYTES;
#pragma unroll
        for (int ks = 0; ks < 2; ks++) {
            const int kb = ks * 16;
            uint32_t a[4][4], b[4][2];
#pragma unroll
            for (int mt = 0; mt < 4; mt++) {
                uint32_t addr = a_base +
                    (uint32_t)((warp_m * 64 + mt * 16 + (lane & 15)) * ASTRH +
                               kb + ((lane >> 4) << 3)) * 2u;
                asm volatile("ldmatrix.sync.aligned.m8n8.x4.shared.b16 {%0,%1,%2,%3}, [%4];"
                             : "=r"(a[mt][0]), "=r"(a[mt][1]), "=r"(a[mt][2]), "=r"(a[mt][3])
                             : "r"(addr));
            }
#pragma unroll
            for (int nt2 = 0; nt2 < 2; nt2++) {
                uint32_t addr = b_base +
                    (uint32_t)((kb + (lane & 15)) * BSTRH +
                               warp_n * 32 + nt2 * 16 + ((lane >> 4) << 3)) * 2u;
                asm volatile("ldmatrix.sync.aligned.m8n8.x4.trans.shared.b16 {%0,%1,%2,%3}, [%4];"
                             : "=r"(b[nt2 * 2][0]), "=r"(b[nt2 * 2][1]),
                               "=r"(b[nt2 * 2 + 1][0]), "=r"(b[nt2 * 2 + 1][1])
                             : "r"(addr));
            }
#pragma unroll
            for (int mt = 0; mt < 4; mt++)
#pragma unroll
                for (int nt = 0; nt < 4; nt++) {
                    asm volatile(
                        "mma.sync.aligned.m16n8k16.row.col.f32.f16.f16.f32 "
                        "{%0,%1,%2,%3}, {%4,%5,%6,%7}, {%8,%9}, {%0,%1,%2,%3};"
                        : "+f"(acc[mt][nt][0]), "+f"(acc[mt][nt][1]),
                          "+f"(acc[mt][nt][2]), "+f"(acc[mt][nt][3])
                        : "r"(a[mt][0]), "r"(a[mt][1]), "r"(a[mt][2]), "r"(a[mt][3]),
                          "r"(b[nt][0]), "r"(b[nt][1]));
                }
        }
    };

    ldg_chunk(0);
    sts_chunk(0);
    __syncthreads();

    for (int ch = 0; ch < n_chunks; ch++) {
        bool next = (ch + 1 < n_chunks);
        if (next) ldg_chunk(ch + 1);
        compute(ch & 1);
        if (next) {
            sts_chunk((ch + 1) & 1);
            __syncthreads();
        }
    }

    // epilogue
#pragma unroll
    for (int mt = 0; mt < 4; mt++) {
#pragma unroll
        for (int half = 0; half < 2; half++) {
            int gr = row0 + warp_m * 64 + mt * 16 + gid + half * 8;
            if (gr >= M) continue;
#pragma unroll
            for (int nt = 0; nt < 4; nt++) {
                int gc = col0 + warp_n * 32 + nt * 8 + t4 * 2;
                if (gc >= N) continue;
                float2 o;
                o.x = acc[mt][nt][half * 2 + 0];
                o.y = acc[mt][nt][half * 2 + 1];
                if (BIAS) {
                    o.x += __ldg(&bias[gc]);
                    o.y += __ldg(&bias[gc + 1]);
                }
                if (RELU) {
                    o.x = fmaxf(o.x, 0.0f);
                    o.y = fmaxf(o.y, 0.0f);
                }
                if (HALF_OUT) {
                    *reinterpret_cast<__half2*>((__half*)Cv + (size_t)gr * N + gc) =
                        __floats2half2_rn(o.x, o.y);
                } else {
                    *reinterpret_cast<float2*>((float*)Cv + (size_t)gr * N + gc) = o;
                }
            }
        }
    }
}

// ---------------- edge dtype detection + conversion -------------------------
__global__ void detect_kernel(const int* __restrict__ e_raw, int n_check) {
    __shared__ int nz;
    if (threadIdx.x == 0) nz = 0;
    __syncthreads();
    for (int i = threadIdx.x; i < n_check; i += blockDim.x)
        if (e_raw[2 * i + 1] != 0) atomicAdd(&nz, 1);
    __syncthreads();
    if (threadIdx.x == 0) g_is64 = (nz == 0) ? 1 : 0;
}

__global__ void convert_count_kernel(const int* __restrict__ e_raw,
                                     int* __restrict__ src32, int* __restrict__ dst32,
                                     int* __restrict__ cnt, int* __restrict__ fill, int E) {
    int i = blockIdx.x * blockDim.x + threadIdx.x;
    if (i < N_NODES) { cnt[i] = 0; fill[i] = 0; }
    if (i >= E) return;
    int s, d;
    if (g_is64) { s = e_raw[2 * i]; d = e_raw[2 * (E + i)]; }
    else        { s = e_raw[i];     d = e_raw[E + i]; }
    src32[i] = s;
    dst32[i] = d;
    atomicAdd(&cnt[d], 1);
}

__global__ void norm_kernel(const int* __restrict__ cnt,
                            float* __restrict__ dinv, float* __restrict__ selfw, int n) {
    int i = blockIdx.x * blockDim.x + threadIdx.x;
    if (i < n) {
        float d = (float)cnt[i] + 1.0f;
        dinv[i]  = rsqrtf(d);
        selfw[i] = 1.0f / d;
    }
}

// ---------------- exclusive scan of cnt -> ptr ------------------------------
__global__ void scan1_kernel(const int* __restrict__ cnt, int* __restrict__ ptr,
                             int* __restrict__ bsum, int n) {
    __shared__ int sh[SCAN_B];
    int b = blockIdx.x;
    int i = b * SCAN_B + threadIdx.x;
    int v = (i < n) ? cnt[i] : 0;
    sh[threadIdx.x] = v;
    __syncthreads();
    for (int off = 1; off < SCAN_B; off <<= 1) {
        int t = (threadIdx.x >= off) ? sh[threadIdx.x - off] : 0;
        __syncthreads();
        sh[threadIdx.x] += t;
        __syncthreads();
    }
    if (i < n) ptr[i] = sh[threadIdx.x] - v;
    if (threadIdx.x == SCAN_B - 1) bsum[b] = sh[SCAN_B - 1];
}

__global__ void scan2_kernel(int* __restrict__ bsum, int nb) {
    __shared__ int sh[256];
    int v = (threadIdx.x < nb) ? bsum[threadIdx.x] : 0;
    sh[threadIdx.x] = v;
    __syncthreads();
    for (int off = 1; off < 256; off <<= 1) {
        int t = (threadIdx.x >= off) ? sh[threadIdx.x - off] : 0;
        __syncthreads();
        sh[threadIdx.x] += t;
        __syncthreads();
    }
    if (threadIdx.x < nb) bsum[threadIdx.x] = sh[threadIdx.x] - v;
}

__global__ void scan3_kernel(int* __restrict__ ptr, const int* __restrict__ bsum,
                             int n, int E) {
    int i = blockIdx.x * SCAN_B + threadIdx.x;
    if (i < n) ptr[i] += bsum[blockIdx.x];
    if (i == n) ptr[n] = E;
}

__global__ void csr_fill_kernel(const int* __restrict__ src, const int* __restrict__ dst,
                                const int* __restrict__ ptr, int* __restrict__ fill,
                                int* __restrict__ csr_src, int E) {
    int i = blockIdx.x * blockDim.x + threadIdx.x;
    if (i >= E) return;
    int s = src[i], d = dst[i];
    int pos = atomicAdd(&fill[d], 1);
    csr_src[ptr[d] + pos] = s;
}

// ---------------- fused aggregation + BN + ReLU + residual ------------------
__global__ void agg_kernel(const int* __restrict__ ptr,
                           const int* __restrict__ csr_src,
                           const float* __restrict__ dinv,
                           const float* __restrict__ selfw,
                           const __half* __restrict__ hw,
                           const float* __restrict__ cb,
                           const float* __restrict__ gamma,
                           const float* __restrict__ beta,
                           float* __restrict__ h, int N)
{
    int d = blockIdx.x * 8 + (threadIdx.x >> 5);
    if (d >= N) return;
    int lane = threadIdx.x & 31;

    float acc[8];
#pragma unroll
    for (int q = 0; q < 8; q++) acc[q] = 0.0f;

    float dv_d = __ldg(&dinv[d]);
    int beg = __ldg(&ptr[d]);
    int end = __ldg(&ptr[d + 1]);
    int j = beg;
    // unroll by 4: four independent row gathers in flight
    for (; j + 4 <= end; j += 4) {
        int s0 = __ldg(&csr_src[j]);
        int s1 = __ldg(&csr_src[j + 1]);
        int s2 = __ldg(&csr_src[j + 2]);
        int s3 = __ldg(&csr_src[j + 3]);
        float w0 = __ldg(&dinv[s0]) * dv_d;
        float w1 = __ldg(&dinv[s1]) * dv_d;
        float w2 = __ldg(&dinv[s2]) * dv_d;
        float w3 = __ldg(&dinv[s3]) * dv_d;
        uint4 v0 = __ldg(reinterpret_cast<const uint4*>(hw + (size_t)s0 * HID) + lane);
        uint4 v1 = __ldg(reinterpret_cast<const uint4*>(hw + (size_t)s1 * HID) + lane);
        uint4 v2 = __ldg(reinterpret_cast<const uint4*>(hw + (size_t)s2 * HID) + lane);
        uint4 v3 = __ldg(reinterpret_cast<const uint4*>(hw + (size_t)s3 * HID) + lane);
        const __half2* p0 = reinterpret_cast<const __half2*>(&v0);
        const __half2* p1 = reinterpret_cast<const __half2*>(&v1);
        const __half2* p2 = reinterpret_cast<const __half2*>(&v2);
        const __half2* p3 = reinterpret_cast<const __half2*>(&v3);
#pragma unroll
        for (int q = 0; q < 4; q++) {
            float2 f0 = __half22float2(p0[q]);
            float2 f1 = __half22float2(p1[q]);
            float2 f2 = __half22float2(p2[q]);
            float2 f3 = __half22float2(p3[q]);
            acc[2 * q]     += f0.x * w0 + f1.x * w1 + f2.x * w2 + f3.x * w3;
            acc[2 * q + 1] += f0.y * w0 + f1.y * w1 + f2.y * w2 + f3.y * w3;
        }
    }
    for (; j < end; j++) {
        int s = __ldg(&csr_src[j]);
        float w = __ldg(&dinv[s]) * dv_d;
        uint4 v = __ldg(reinterpret_cast<const uint4*>(hw + (size_t)s * HID) + lane);
        const __half2* p = reinterpret_cast<const __half2*>(&v);
#pragma unroll
        for (int q = 0; q < 4; q++) {
            float2 f = __half22float2(p[q]);
            acc[2 * q]     = fmaf(f.x, w, acc[2 * q]);
            acc[2 * q + 1] = fmaf(f.y, w, acc[2 * q + 1]);
        }
    }

    float sw = __ldg(&selfw[d]);
    uint4 v = __ldg(reinterpret_cast<const uint4*>(hw + (size_t)d * HID) + lane);
    const __half2* p = reinterpret_cast<const __half2*>(&v);
#pragma unroll
    for (int q = 0; q < 4; q++) {
        float2 f = __half22float2(p[q]);
        acc[2 * q]     = fmaf(f.x, sw, acc[2 * q]);
        acc[2 * q + 1] = fmaf(f.y, sw, acc[2 * q + 1]);
    }

    const float4* cb4 = reinterpret_cast<const float4*>(cb);
    const float4* g4  = reinterpret_cast<const float4*>(gamma);
    const float4* bt4 = reinterpret_cast<const float4*>(beta);
    float4* hrow = reinterpret_cast<float4*>(h + (size_t)d * HID);

#pragma unroll
    for (int q2 = 0; q2 < 2; q2++) {
        int c4i = lane * 2 + q2;
        float4 b  = __ldg(&cb4[c4i]);
        float4 g  = __ldg(&g4[c4i]);
        float4 bt = __ldg(&bt4[c4i]);
        float4 hv = hrow[c4i];
        hv.x += fmaxf(fmaf(acc[q2 * 4 + 0] + b.x, g.x, bt.x), 0.0f);
        hv.y += fmaxf(fmaf(acc[q2 * 4 + 1] + b.y, g.y, bt.y), 0.0f);
        hv.z += fmaxf(fmaf(acc[q2 * 4 + 2] + b.z, g.z, bt.z), 0.0f);
        hv.w += fmaxf(fmaf(acc[q2 * 4 + 3] + b.w, g.w, bt.w), 0.0f);
        hrow[c4i] = hv;
    }
}

// ---------------- fused classifier tail: c2 -> relu -> c3 -> out ------------
// thread per row; W2 (64x32), W3 (32x40) broadcast from smem.
__global__ void __launch_bounds__(256) cls_tail_kernel(
    const float* __restrict__ c2in,
    const float* __restrict__ W2, const float* __restrict__ b2,
    const float* __restrict__ W3, const float* __restrict__ b3,
    float* __restrict__ out, int N)
{
    __shared__ float sW2[64 * 32];
    __shared__ float sW3[32 * 40];
    __shared__ float sb2[32];
    __shared__ float sb3[40];
    for (int i = threadIdx.x; i < 64 * 32; i += 256) sW2[i] = W2[i];
    for (int i = threadIdx.x; i < 32 * 40; i += 256) sW3[i] = W3[i];
    if (threadIdx.x < 32) sb2[threadIdx.x] = b2[threadIdx.x];
    if (threadIdx.x < 40) sb3[threadIdx.x] = b3[threadIdx.x];
    __syncthreads();

    int r = blockIdx.x * 256 + threadIdx.x;
    if (r >= N) return;

    float x[64];
    const float4* row = reinterpret_cast<const float4*>(c2in + (size_t)r * 64);
#pragma unroll
    for (int q = 0; q < 16; q++) {
        float4 v = __ldg(&row[q]);
        x[4 * q] = v.x; x[4 * q + 1] = v.y; x[4 * q + 2] = v.z; x[4 * q + 3] = v.w;
    }

    float h2[32];
#pragma unroll
    for (int n = 0; n < 32; n++) h2[n] = sb2[n];
#pragma unroll 8
    for (int k = 0; k < 64; k++) {
        float xk = x[k];
#pragma unroll
        for (int n = 0; n < 32; n++)
            h2[n] = fmaf(xk, sW2[k * 32 + n], h2[n]);
    }
#pragma unroll
    for (int n = 0; n < 32; n++) h2[n] = fmaxf(h2[n], 0.0f);

    float* orow = out + (size_t)r * 40;
#pragma unroll
    for (int n = 0; n < 40; n++) {
        float o = sb3[n];
#pragma unroll
        for (int k = 0; k < 32; k++)
            o = fmaf(h2[k], sW3[k * 40 + n], o);
        orow[n] = o;
    }
}

// ---------------- host launcher ---------------------------------------------
template<bool BIAS, bool RELU, bool HALF_OUT>
static void launch_mma_gemm(const float* A, const float* W, const float* bias, void* C,
                            int M, int N, int K) {
    cudaFuncSetAttribute(mma_gemm_kernel<BIAS, RELU, HALF_OUT>,
                         cudaFuncAttributeMaxDynamicSharedMemorySize, MMA_SMEM);
    dim3 grid((N + 127) / 128, (M + 127) / 128);
    mma_gemm_kernel<BIAS, RELU, HALF_OUT><<<grid, 256, MMA_SMEM>>>(A, W, bias, C, M, N, K);
}

extern "C" void kernel_launch(void* const* d_in, const int* in_sizes, int n_in,
                              void* d_out, int out_size)
{
    const float* x      = (const float*)d_in[0];
    const int*   e_raw  = (const int*)d_in[1];
    const float* embW   = (const float*)d_in[2];
    const float* embB   = (const float*)d_in[3];
    const float* convW  = (const float*)d_in[4];
    const float* convB  = (const float*)d_in[5];
    const float* gamma  = (const float*)d_in[6];
    const float* beta   = (const float*)d_in[7];
    const float* W0 = (const float*)d_in[8];
    const float* b0 = (const float*)d_in[9];
    const float* W1 = (const float*)d_in[10];
    const float* b1 = (const float*)d_in[11];
    const float* W2 = (const float*)d_in[12];
    const float* b2 = (const float*)d_in[13];
    const float* W3 = (const float*)d_in[14];
    const float* b3 = (const float*)d_in[15];
    float* out = (float*)d_out;

    const int N = N_NODES;
    const int E = in_sizes[1] / 2;

    float *h, *dinv, *selfw, *c1, *c2;
    __half* hw;
    int *src32, *dst32, *cnt, *ptr, *fill, *csr_src, *bsum;
    cudaGetSymbolAddress((void**)&h,       g_h);
    cudaGetSymbolAddress((void**)&hw,      g_hw);
    cudaGetSymbolAddress((void**)&dinv,    g_dinv);
    cudaGetSymbolAddress((void**)&selfw,   g_self);
    cudaGetSymbolAddress((void**)&c1,      g_c1);
    cudaGetSymbolAddress((void**)&c2,      g_c2);
    cudaGetSymbolAddress((void**)&src32,   g_src32);
    cudaGetSymbolAddress((void**)&dst32,   g_dst32);
    cudaGetSymbolAddress((void**)&cnt,     g_cnt);
    cudaGetSymbolAddress((void**)&ptr,     g_ptr);
    cudaGetSymbolAddress((void**)&fill,    g_fill);
    cudaGetSymbolAddress((void**)&csr_src, g_csr_src);
    cudaGetSymbolAddress((void**)&bsum,    g_bsum);

    int nb = (N + SCAN_B - 1) / SCAN_B;

    // edge prep + CSR build
    detect_kernel<<<1, 256>>>(e_raw, 1024);
    convert_count_kernel<<<(E + 255) / 256, 256>>>(e_raw, src32, dst32, cnt, fill, E);
    norm_kernel<<<(N + 255) / 256, 256>>>(cnt, dinv, selfw, N);
    scan1_kernel<<<nb, SCAN_B>>>(cnt, ptr, bsum, N);
    scan2_kernel<<<1, 256>>>(bsum, nb);

    // embed GEMM (independent of CSR build)
    launch_mma_gemm<true, false, false>(x, embW, embB, h, N, HID, 500);

    scan3_kernel<<<nb + 1, SCAN_B>>>(ptr, bsum, N, E);
    csr_fill_kernel<<<(E + 255) / 256, 256>>>(src32, dst32, ptr, fill, csr_src, E);

    // GCN layers
    const int agg_blocks = (N + 7) / 8;
    for (int l = 0; l < 3; l++) {
        const float* Wl  = convW + (size_t)l * HID * HID;
        const float* cbl = convB + (size_t)l * HID;
        const float* gl  = gamma + (size_t)l * HID;
        const float* btl = beta  + (size_t)l * HID;

        launch_mma_gemm<false, false, true>(h, Wl, nullptr, hw, N, HID, HID);
        agg_kernel<<<agg_blocks, 256>>>(ptr, csr_src, dinv, selfw, hw, cbl, gl, btl, h, N);
    }

    // classifier MLP: two tensor GEMMs + fused SIMT tail
    launch_mma_gemm<true, true, false>(h,  W0, b0, c1, N, 128, 256);
    launch_mma_gemm<true, true, false>(c1, W1, b1, c2, N, 64,  128);
    cls_tail_kernel<<<(N + 255) / 256, 256>>>(c2, W2, b2, W3, b3, out, N);
}

// round 12
// speedup vs baseline: 1.3054x; 1.0022x over previous
#include <cuda_runtime.h>
#include <cuda_fp16.h>
#include <stdint.h>

#define N_NODES 100000
#define N_EDGES 1600000
#define HID 256
#define SCAN_B 1024

// ---------------- scratch (device globals; no allocation allowed) ----------
__device__ float  g_h[(size_t)N_NODES * HID];
__device__ __half g_h16[(size_t)N_NODES * HID];   // fp16 shadow of h (A operand)
__device__ __half g_hw[(size_t)N_NODES * HID];
__device__ float  g_dinv[N_NODES];
__device__ float  g_self[N_NODES];
__device__ __half g_c1[(size_t)N_NODES * 128];
__device__ float  g_c2[(size_t)N_NODES * 64];
__device__ int    g_src32[N_EDGES];
__device__ int    g_dst32[N_EDGES];
__device__ int    g_cnt[N_NODES];
__device__ int    g_ptr[N_NODES + 1];
__device__ int    g_fill[N_NODES];
__device__ int    g_csr_src[N_EDGES];
__device__ int    g_bsum[(N_NODES + SCAN_B - 1) / SCAN_B + 1];
__device__ int    g_is64;

__device__ __forceinline__ uint32_t smem_u32(const void* p) {
    uint32_t a;
    asm("{ .reg .u64 t; cvta.to.shared.u64 t, %1; cvt.u32.u64 %0, t; }" : "=r"(a) : "l"(p));
    return a;
}
__device__ __forceinline__ uint32_t packh2(float lo, float hi) {
    uint32_t o;
    asm("cvt.rn.f16x2.f32 %0, %1, %2;" : "=r"(o) : "f"(hi), "f"(lo));
    return o;
}

// ====== fp16 mma m16n8k16 GEMM with ldmatrix fragments =======================
// CTA tile 128x128, BK=32, 8 warps (2 M x 4 N), warp tile 64x32.
// OUTMODE: 0 = fp32 C, 1 = fp16 C2, 2 = both. AHALF: A source already fp16.
#define ASTRH 40
#define BSTRH 136
#define A_BYTES (128 * ASTRH * 2)
#define B_BYTES (32 * BSTRH * 2)
#define STG_BYTES (A_BYTES + B_BYTES)
#define MMA_SMEM (2 * STG_BYTES)

template<int OUTMODE, bool BIAS, bool RELU, bool AHALF>
__global__ void __launch_bounds__(256, 2) mma_gemm_kernel(
    const void* __restrict__ Av, const float* __restrict__ W,
    const float* __restrict__ bias,
    float* __restrict__ C, __half* __restrict__ C2,
    int M, int N, int K)
{
    extern __shared__ char smc[];
    const uint32_t sbase = smem_u32(smc);

    const int tid    = threadIdx.x;
    const int wid    = tid >> 5;
    const int lane   = tid & 31;
    const int gid    = lane >> 2;
    const int t4     = lane & 3;
    const int warp_m = wid >> 2;
    const int warp_n = wid & 3;
    const int row0   = blockIdx.y * 128;
    const int col0   = blockIdx.x * 128;

    float acc[4][4][4];
#pragma unroll
    for (int mt = 0; mt < 4; mt++)
#pragma unroll
        for (int nt = 0; nt < 4; nt++)
#pragma unroll
            for (int q = 0; q < 4; q++) acc[mt][nt][q] = 0.0f;

    const int n_chunks = (K + 31) / 32;
    float4 pa[4];      // fp32 A path
    uint4  pah[2];     // fp16 A path
    float4 pb[4];

    auto ldg_chunk = [&](int ch) {
        const int k0 = ch * 32;
        if (AHALF) {
            const __half* A = (const __half*)Av;
#pragma unroll
            for (int t = 0; t < 2; t++) {
                int i  = tid + t * 256;            // 0..511
                int r  = i >> 2, c8 = (i & 3) * 8;
                int gr = row0 + r, gk = k0 + c8;
                if (gr < M && gk + 8 <= K)
                    pah[t] = *reinterpret_cast<const uint4*>(A + (size_t)gr * K + gk);
                else
                    pah[t] = make_uint4(0u, 0u, 0u, 0u);
            }
        } else {
            const float* A = (const float*)Av;
#pragma unroll
            for (int t = 0; t < 4; t++) {
                int i  = tid + t * 256;
                int r  = i >> 3, c4 = (i & 7) * 4;
                int gr = row0 + r, gk = k0 + c4;
                if (gr < M && gk + 4 <= K)
                    pa[t] = *reinterpret_cast<const float4*>(A + (size_t)gr * K + gk);
                else
                    pa[t] = make_float4(0.f, 0.f, 0.f, 0.f);
            }
        }
#pragma unroll
        for (int t = 0; t < 4; t++) {
            int i  = tid + t * 256;
            int r  = i >> 5, c4 = (i & 31) * 4;
            int gk = k0 + r, gn = col0 + c4;
            if (gk < K && gn + 4 <= N)
                pb[t] = *reinterpret_cast<const float4*>(W + (size_t)gk * N + gn);
            else
                pb[t] = make_float4(0.f, 0.f, 0.f, 0.f);
        }
    };

    auto sts_chunk = [&](int st) {
        if (AHALF) {
#pragma unroll
            for (int t = 0; t < 2; t++) {
                int i = tid + t * 256;
                int r = i >> 2, c8 = (i & 3) * 8;
                *reinterpret_cast<uint4*>(smc + (st * STG_BYTES) + r * (ASTRH * 2) + c8 * 2) = pah[t];
            }
        } else {
#pragma unroll
            for (int t = 0; t < 4; t++) {
                int i = tid + t * 256;
                int r = i >> 3, c4 = i & 7;
                uint2 v = make_uint2(packh2(pa[t].x, pa[t].y), packh2(pa[t].z, pa[t].w));
                *reinterpret_cast<uint2*>(smc + (st * STG_BYTES) + r * (ASTRH * 2) + c4 * 8) = v;
            }
        }
#pragma unroll
        for (int t = 0; t < 4; t++) {
            int i = tid + t * 256;
            int r = i >> 5, c4 = i & 31;
            uint2 v = make_uint2(packh2(pb[t].x, pb[t].y), packh2(pb[t].z, pb[t].w));
            *reinterpret_cast<uint2*>(smc + (st * STG_BYTES) + A_BYTES + r * (BSTRH * 2) + c4 * 8) = v;
        }
    };

    auto compute = [&](int st) {
        const uint32_t a_base = sbase + (uint32_t)st * STG_BYTES;
        const uint32_t b_base = a_base + A_BYTES;
#pragma unroll
        for (int ks = 0; ks < 2; ks++) {
            const int kb = ks * 16;
            uint32_t a[4][4], b[4][2];
#pragma unroll
            for (int mt = 0; mt < 4; mt++) {
                uint32_t addr = a_base +
                    (uint32_t)((warp_m * 64 + mt * 16 + (lane & 15)) * ASTRH +
                               kb + ((lane >> 4) << 3)) * 2u;
                asm volatile("ldmatrix.sync.aligned.m8n8.x4.shared.b16 {%0,%1,%2,%3}, [%4];"
                             : "=r"(a[mt][0]), "=r"(a[mt][1]), "=r"(a[mt][2]), "=r"(a[mt][3])
                             : "r"(addr));
            }
#pragma unroll
            for (int nt2 = 0; nt2 < 2; nt2++) {
                uint32_t addr = b_base +
                    (uint32_t)((kb + (lane & 15)) * BSTRH +
                               warp_n * 32 + nt2 * 16 + ((lane >> 4) << 3)) * 2u;
                asm volatile("ldmatrix.sync.aligned.m8n8.x4.trans.shared.b16 {%0,%1,%2,%3}, [%4];"
                             : "=r"(b[nt2 * 2][0]), "=r"(b[nt2 * 2][1]),
                               "=r"(b[nt2 * 2 + 1][0]), "=r"(b[nt2 * 2 + 1][1])
                             : "r"(addr));
            }
#pragma unroll
            for (int mt = 0; mt < 4; mt++)
#pragma unroll
                for (int nt = 0; nt < 4; nt++) {
                    asm volatile(
                        "mma.sync.aligned.m16n8k16.row.col.f32.f16.f16.f32 "
                        "{%0,%1,%2,%3}, {%4,%5,%6,%7}, {%8,%9}, {%0,%1,%2,%3};"
                        : "+f"(acc[mt][nt][0]), "+f"(acc[mt][nt][1]),
                          "+f"(acc[mt][nt][2]), "+f"(acc[mt][nt][3])
                        : "r"(a[mt][0]), "r"(a[mt][1]), "r"(a[mt][2]), "r"(a[mt][3]),
                          "r"(b[nt][0]), "r"(b[nt][1]));
                }
        }
    };

    ldg_chunk(0);
    sts_chunk(0);
    __syncthreads();

    for (int ch = 0; ch < n_chunks; ch++) {
        bool next = (ch + 1 < n_chunks);
        if (next) ldg_chunk(ch + 1);
        compute(ch & 1);
        if (next) {
            sts_chunk((ch + 1) & 1);
            __syncthreads();
        }
    }

    // epilogue
#pragma unroll
    for (int mt = 0; mt < 4; mt++) {
#pragma unroll
        for (int half = 0; half < 2; half++) {
            int gr = row0 + warp_m * 64 + mt * 16 + gid + half * 8;
            if (gr >= M) continue;
#pragma unroll
            for (int nt = 0; nt < 4; nt++) {
                int gc = col0 + warp_n * 32 + nt * 8 + t4 * 2;
                if (gc >= N) continue;
                float2 o;
                o.x = acc[mt][nt][half * 2 + 0];
                o.y = acc[mt][nt][half * 2 + 1];
                if (BIAS) {
                    o.x += __ldg(&bias[gc]);
                    o.y += __ldg(&bias[gc + 1]);
                }
                if (RELU) {
                    o.x = fmaxf(o.x, 0.0f);
                    o.y = fmaxf(o.y, 0.0f);
                }
                if (OUTMODE == 0 || OUTMODE == 2)
                    *reinterpret_cast<float2*>(C + (size_t)gr * N + gc) = o;
                if (OUTMODE >= 1)
                    *reinterpret_cast<__half2*>(C2 + (size_t)gr * N + gc) =
                        __floats2half2_rn(o.x, o.y);
            }
        }
    }
}

// ---------------- edge dtype detection + conversion -------------------------
__global__ void detect_kernel(const int* __restrict__ e_raw, int n_check) {
    __shared__ int nz;
    if (threadIdx.x == 0) nz = 0;
    __syncthreads();
    for (int i = threadIdx.x; i < n_check; i += blockDim.x)
        if (e_raw[2 * i + 1] != 0) atomicAdd(&nz, 1);
    __syncthreads();
    if (threadIdx.x == 0) g_is64 = (nz == 0) ? 1 : 0;
}

__global__ void convert_count_kernel(const int* __restrict__ e_raw,
                                     int* __restrict__ src32, int* __restrict__ dst32,
                                     int* __restrict__ cnt, int* __restrict__ fill, int E) {
    int i = blockIdx.x * blockDim.x + threadIdx.x;
    if (i < N_NODES) { cnt[i] = 0; fill[i] = 0; }
    if (i >= E) return;
    int s, d;
    if (g_is64) { s = e_raw[2 * i]; d = e_raw[2 * (E + i)]; }
    else        { s = e_raw[i];     d = e_raw[E + i]; }
    src32[i] = s;
    dst32[i] = d;
    atomicAdd(&cnt[d], 1);
}

__global__ void norm_kernel(const int* __restrict__ cnt,
                            float* __restrict__ dinv, float* __restrict__ selfw, int n) {
    int i = blockIdx.x * blockDim.x + threadIdx.x;
    if (i < n) {
        float d = (float)cnt[i] + 1.0f;
        dinv[i]  = rsqrtf(d);
        selfw[i] = 1.0f / d;
    }
}

// ---------------- exclusive scan of cnt -> ptr ------------------------------
__global__ void scan1_kernel(const int* __restrict__ cnt, int* __restrict__ ptr,
                             int* __restrict__ bsum, int n) {
    __shared__ int sh[SCAN_B];
    int b = blockIdx.x;
    int i = b * SCAN_B + threadIdx.x;
    int v = (i < n) ? cnt[i] : 0;
    sh[threadIdx.x] = v;
    __syncthreads();
    for (int off = 1; off < SCAN_B; off <<= 1) {
        int t = (threadIdx.x >= off) ? sh[threadIdx.x - off] : 0;
        __syncthreads();
        sh[threadIdx.x] += t;
        __syncthreads();
    }
    if (i < n) ptr[i] = sh[threadIdx.x] - v;
    if (threadIdx.x == SCAN_B - 1) bsum[b] = sh[SCAN_B - 1];
}

__global__ void scan2_kernel(int* __restrict__ bsum, int nb) {
    __shared__ int sh[256];
    int v = (threadIdx.x < nb) ? bsum[threadIdx.x] : 0;
    sh[threadIdx.x] = v;
    __syncthreads();
    for (int off = 1; off < 256; off <<= 1) {
        int t = (threadIdx.x >= off) ? sh[threadIdx.x - off] : 0;
        __syncthreads();
        sh[threadIdx.x] += t;
        __syncthreads();
    }
    if (threadIdx.x < nb) bsum[threadIdx.x] = sh[threadIdx.x] - v;
}

__global__ void scan3_kernel(int* __restrict__ ptr, const int* __restrict__ bsum,
                             int n, int E) {
    int i = blockIdx.x * SCAN_B + threadIdx.x;
    if (i < n) ptr[i] += bsum[blockIdx.x];
    if (i == n) ptr[n] = E;
}

__global__ void csr_fill_kernel(const int* __restrict__ src, const int* __restrict__ dst,
                                const int* __restrict__ ptr, int* __restrict__ fill,
                                int* __restrict__ csr_src, int E) {
    int i = blockIdx.x * blockDim.x + threadIdx.x;
    if (i >= E) return;
    int s = src[i], d = dst[i];
    int pos = atomicAdd(&fill[d], 1);
    csr_src[ptr[d] + pos] = s;
}

// ---------------- fused aggregation + BN + ReLU + residual ------------------
// Also writes fp16 shadow of updated h (zero extra rounding: GEMM converts anyway).
__global__ void agg_kernel(const int* __restrict__ ptr,
                           const int* __restrict__ csr_src,
                           const float* __restrict__ dinv,
                           const float* __restrict__ selfw,
                           const __half* __restrict__ hw,
                           const float* __restrict__ cb,
                           const float* __restrict__ gamma,
                           const float* __restrict__ beta,
                           float* __restrict__ h,
                           __half* __restrict__ h16, int N)
{
    int d = blockIdx.x * 8 + (threadIdx.x >> 5);
    if (d >= N) return;
    int lane = threadIdx.x & 31;

    float acc[8];
#pragma unroll
    for (int q = 0; q < 8; q++) acc[q] = 0.0f;

    float dv_d = __ldg(&dinv[d]);
    int beg = __ldg(&ptr[d]);
    int end = __ldg(&ptr[d + 1]);
    int j = beg;
    for (; j + 4 <= end; j += 4) {
        int s0 = __ldg(&csr_src[j]);
        int s1 = __ldg(&csr_src[j + 1]);
        int s2 = __ldg(&csr_src[j + 2]);
        int s3 = __ldg(&csr_src[j + 3]);
        float w0 = __ldg(&dinv[s0]) * dv_d;
        float w1 = __ldg(&dinv[s1]) * dv_d;
        float w2 = __ldg(&dinv[s2]) * dv_d;
        float w3 = __ldg(&dinv[s3]) * dv_d;
        uint4 v0 = __ldg(reinterpret_cast<const uint4*>(hw + (size_t)s0 * HID) + lane);
        uint4 v1 = __ldg(reinterpret_cast<const uint4*>(hw + (size_t)s1 * HID) + lane);
        uint4 v2 = __ldg(reinterpret_cast<const uint4*>(hw + (size_t)s2 * HID) + lane);
        uint4 v3 = __ldg(reinterpret_cast<const uint4*>(hw + (size_t)s3 * HID) + lane);
        const __half2* p0 = reinterpret_cast<const __half2*>(&v0);
        const __half2* p1 = reinterpret_cast<const __half2*>(&v1);
        const __half2* p2 = reinterpret_cast<const __half2*>(&v2);
        const __half2* p3 = reinterpret_cast<const __half2*>(&v3);
#pragma unroll
        for (int q = 0; q < 4; q++) {
            float2 f0 = __half22float2(p0[q]);
            float2 f1 = __half22float2(p1[q]);
            float2 f2 = __half22float2(p2[q]);
            float2 f3 = __half22float2(p3[q]);
            acc[2 * q]     += f0.x * w0 + f1.x * w1 + f2.x * w2 + f3.x * w3;
            acc[2 * q + 1] += f0.y * w0 + f1.y * w1 + f2.y * w2 + f3.y * w3;
        }
    }
    for (; j < end; j++) {
        int s = __ldg(&csr_src[j]);
        float w = __ldg(&dinv[s]) * dv_d;
        uint4 v = __ldg(reinterpret_cast<const uint4*>(hw + (size_t)s * HID) + lane);
        const __half2* p = reinterpret_cast<const __half2*>(&v);
#pragma unroll
        for (int q = 0; q < 4; q++) {
            float2 f = __half22float2(p[q]);
            acc[2 * q]     = fmaf(f.x, w, acc[2 * q]);
            acc[2 * q + 1] = fmaf(f.y, w, acc[2 * q + 1]);
        }
    }

    float sw = __ldg(&selfw[d]);
    uint4 v = __ldg(reinterpret_cast<const uint4*>(hw + (size_t)d * HID) + lane);
    const __half2* p = reinterpret_cast<const __half2*>(&v);
#pragma unroll
    for (int q = 0; q < 4; q++) {
        float2 f = __half22float2(p[q]);
        acc[2 * q]     = fmaf(f.x, sw, acc[2 * q]);
        acc[2 * q + 1] = fmaf(f.y, sw, acc[2 * q + 1]);
    }

    const float4* cb4 = reinterpret_cast<const float4*>(cb);
    const float4* g4  = reinterpret_cast<const float4*>(gamma);
    const float4* bt4 = reinterpret_cast<const float4*>(beta);
    float4* hrow = reinterpret_cast<float4*>(h + (size_t)d * HID);

    uint32_t o16[4];
#pragma unroll
    for (int q2 = 0; q2 < 2; q2++) {
        int c4i = lane * 2 + q2;
        float4 b  = __ldg(&cb4[c4i]);
        float4 g  = __ldg(&g4[c4i]);
        float4 bt = __ldg(&bt4[c4i]);
        float4 hv = hrow[c4i];
        hv.x += fmaxf(fmaf(acc[q2 * 4 + 0] + b.x, g.x, bt.x), 0.0f);
        hv.y += fmaxf(fmaf(acc[q2 * 4 + 1] + b.y, g.y, bt.y), 0.0f);
        hv.z += fmaxf(fmaf(acc[q2 * 4 + 2] + b.z, g.z, bt.z), 0.0f);
        hv.w += fmaxf(fmaf(acc[q2 * 4 + 3] + b.w, g.w, bt.w), 0.0f);
        hrow[c4i] = hv;
        o16[q2 * 2]     = packh2(hv.x, hv.y);
        o16[q2 * 2 + 1] = packh2(hv.z, hv.w);
    }
    *reinterpret_cast<uint4*>(h16 + (size_t)d * HID + 8 * lane) =
        make_uint4(o16[0], o16[1], o16[2], o16[3]);
}

// ---------------- fused classifier tail: c2 -> relu -> c3 -> out ------------
__global__ void __launch_bounds__(256) cls_tail_kernel(
    const float* __restrict__ c2in,
    const float* __restrict__ W2, const float* __restrict__ b2,
    const float* __restrict__ W3, const float* __restrict__ b3,
    float* __restrict__ out, int N)
{
    __shared__ float sW2[64 * 32];
    __shared__ float sW3[32 * 40];
    __shared__ float sb2[32];
    __shared__ float sb3[40];
    for (int i = threadIdx.x; i < 64 * 32; i += 256) sW2[i] = W2[i];
    for (int i = threadIdx.x; i < 32 * 40; i += 256) sW3[i] = W3[i];
    if (threadIdx.x < 32) sb2[threadIdx.x] = b2[threadIdx.x];
    if (threadIdx.x < 40) sb3[threadIdx.x] = b3[threadIdx.x];
    __syncthreads();

    int r = blockIdx.x * 256 + threadIdx.x;
    if (r >= N) return;

    float x[64];
    const float4* row = reinterpret_cast<const float4*>(c2in + (size_t)r * 64);
#pragma unroll
    for (int q = 0; q < 16; q++) {
        float4 v = __ldg(&row[q]);
        x[4 * q] = v.x; x[4 * q + 1] = v.y; x[4 * q + 2] = v.z; x[4 * q + 3] = v.w;
    }

    float h2[32];
#pragma unroll
    for (int n = 0; n < 32; n++) h2[n] = sb2[n];
#pragma unroll 8
    for (int k = 0; k < 64; k++) {
        float xk = x[k];
#pragma unroll
        for (int n = 0; n < 32; n++)
            h2[n] = fmaf(xk, sW2[k * 32 + n], h2[n]);
    }
#pragma unroll
    for (int n = 0; n < 32; n++) h2[n] = fmaxf(h2[n], 0.0f);

    float* orow = out + (size_t)r * 40;
#pragma unroll
    for (int n = 0; n < 40; n++) {
        float o = sb3[n];
#pragma unroll
        for (int k = 0; k < 32; k++)
            o = fmaf(h2[k], sW3[k * 40 + n], o);
        orow[n] = o;
    }
}

// ---------------- host launcher ---------------------------------------------
template<int OUTMODE, bool BIAS, bool RELU, bool AHALF>
static void launch_mma_gemm(const void* A, const float* W, const float* bias,
                            float* C, __half* C2, int M, int N, int K) {
    cudaFuncSetAttribute(mma_gemm_kernel<OUTMODE, BIAS, RELU, AHALF>,
                         cudaFuncAttributeMaxDynamicSharedMemorySize, MMA_SMEM);
    dim3 grid((N + 127) / 128, (M + 127) / 128);
    mma_gemm_kernel<OUTMODE, BIAS, RELU, AHALF><<<grid, 256, MMA_SMEM>>>(A, W, bias, C, C2, M, N, K);
}

extern "C" void kernel_launch(void* const* d_in, const int* in_sizes, int n_in,
                              void* d_out, int out_size)
{
    const float* x      = (const float*)d_in[0];
    const int*   e_raw  = (const int*)d_in[1];
    const float* embW   = (const float*)d_in[2];
    const float* embB   = (const float*)d_in[3];
    const float* convW  = (const float*)d_in[4];
    const float* convB  = (const float*)d_in[5];
    const float* gamma  = (const float*)d_in[6];
    const float* beta   = (const float*)d_in[7];
    const float* W0 = (const float*)d_in[8];
    const float* b0 = (const float*)d_in[9];
    const float* W1 = (const float*)d_in[10];
    const float* b1 = (const float*)d_in[11];
    const float* W2 = (const float*)d_in[12];
    const float* b2 = (const float*)d_in[13];
    const float* W3 = (const float*)d_in[14];
    const float* b3 = (const float*)d_in[15];
    float* out = (float*)d_out;

    const int N = N_NODES;
    const int E = in_sizes[1] / 2;

    float *h, *dinv, *selfw, *c2;
    __half *hw, *h16, *c1;
    int *src32, *dst32, *cnt, *ptr, *fill, *csr_src, *bsum;
    cudaGetSymbolAddress((void**)&h,       g_h);
    cudaGetSymbolAddress((void**)&h16,     g_h16);
    cudaGetSymbolAddress((void**)&hw,      g_hw);
    cudaGetSymbolAddress((void**)&dinv,    g_dinv);
    cudaGetSymbolAddress((void**)&selfw,   g_self);
    cudaGetSymbolAddress((void**)&c1,      g_c1);
    cudaGetSymbolAddress((void**)&c2,      g_c2);
    cudaGetSymbolAddress((void**)&src32,   g_src32);
    cudaGetSymbolAddress((void**)&dst32,   g_dst32);
    cudaGetSymbolAddress((void**)&cnt,     g_cnt);
    cudaGetSymbolAddress((void**)&ptr,     g_ptr);
    cudaGetSymbolAddress((void**)&fill,    g_fill);
    cudaGetSymbolAddress((void**)&csr_src, g_csr_src);
    cudaGetSymbolAddress((void**)&bsum,    g_bsum);

    int nb = (N + SCAN_B - 1) / SCAN_B;

    // edge prep + CSR build
    detect_kernel<<<1, 256>>>(e_raw, 1024);
    convert_count_kernel<<<(E + 255) / 256, 256>>>(e_raw, src32, dst32, cnt, fill, E);
    norm_kernel<<<(N + 255) / 256, 256>>>(cnt, dinv, selfw, N);
    scan1_kernel<<<nb, SCAN_B>>>(cnt, ptr, bsum, N);
    scan2_kernel<<<1, 256>>>(bsum, nb);

    // embed GEMM: h (fp32) + h16 shadow
    launch_mma_gemm<2, true, false, false>(x, embW, embB, h, h16, N, HID, 500);

    scan3_kernel<<<nb + 1, SCAN_B>>>(ptr, bsum, N, E);
    csr_fill_kernel<<<(E + 255) / 256, 256>>>(src32, dst32, ptr, fill, csr_src, E);

    // GCN layers: fp16-A tensor GEMM + fused aggregation (writes h + h16)
    const int agg_blocks = (N + 7) / 8;
    for (int l = 0; l < 3; l++) {
        const float* Wl  = convW + (size_t)l * HID * HID;
        const float* cbl = convB + (size_t)l * HID;
        const float* gl  = gamma + (size_t)l * HID;
        const float* btl = beta  + (size_t)l * HID;

        launch_mma_gemm<1, false, false, true>(h16, Wl, nullptr, nullptr, hw, N, HID, HID);
        agg_kernel<<<agg_blocks, 256>>>(ptr, csr_src, dinv, selfw, hw, cbl, gl, btl, h, h16, N);
    }

    // classifier MLP: fp16-A chain + fused SIMT tail
    launch_mma_gemm<1, true, true, true>(h16, W0, b0, nullptr, c1, N, 128, 256);
    launch_mma_gemm<0, true, true, true>(c1, W1, b1, c2, nullptr, N, 64, 128);
    cls_tail_kernel<<<(N + 255) / 256, 256>>>(c2, W2, b2, W3, b3, out, N);
}

// round 13
// speedup vs baseline: 1.3295x; 1.0184x over previous
#include <cuda_runtime.h>
#include <cuda_fp16.h>
#include <stdint.h>

#define N_NODES 100000
#define N_EDGES 1600000
#define HID 256
#define SCAN_B 1024

// ---------------- scratch (device globals; no allocation allowed) ----------
__device__ float  g_h[(size_t)N_NODES * HID];
__device__ __half g_h16[(size_t)N_NODES * HID];
__device__ __half g_hw[(size_t)N_NODES * HID];
__device__ float  g_dinv[N_NODES];
__device__ float  g_self[N_NODES];
__device__ __half g_c1[(size_t)N_NODES * 128];
__device__ float  g_c2[(size_t)N_NODES * 64];
__device__ int    g_src32[N_EDGES];
__device__ int    g_dst32[N_EDGES];
__device__ int    g_cnt[N_NODES];
__device__ int    g_ptr[N_NODES + 1];
__device__ int    g_fill[N_NODES];
__device__ int    g_csr_src[N_EDGES];
__device__ int    g_bsum[(N_NODES + SCAN_B - 1) / SCAN_B + 1];
__device__ int    g_is64;

__device__ __forceinline__ uint32_t smem_u32(const void* p) {
    uint32_t a;
    asm("{ .reg .u64 t; cvta.to.shared.u64 t, %1; cvt.u32.u64 %0, t; }" : "=r"(a) : "l"(p));
    return a;
}
__device__ __forceinline__ uint32_t packh2(float lo, float hi) {
    uint32_t o;
    asm("cvt.rn.f16x2.f32 %0, %1, %2;" : "=r"(o) : "f"(hi), "f"(lo));
    return o;
}

// ====== fp16 mma m16n8k16 GEMM with ldmatrix fragments =======================
#define ASTRH 40
#define BSTRH 136
#define A_BYTES (128 * ASTRH * 2)
#define B_BYTES (32 * BSTRH * 2)
#define STG_BYTES (A_BYTES + B_BYTES)
#define MMA_SMEM (2 * STG_BYTES)

template<int OUTMODE, bool BIAS, bool RELU, bool AHALF>
__global__ void __launch_bounds__(256, 2) mma_gemm_kernel(
    const void* __restrict__ Av, const float* __restrict__ W,
    const float* __restrict__ bias,
    float* __restrict__ C, __half* __restrict__ C2,
    int M, int N, int K)
{
    extern __shared__ char smc[];
    const uint32_t sbase = smem_u32(smc);

    const int tid    = threadIdx.x;
    const int wid    = tid >> 5;
    const int lane   = tid & 31;
    const int gid    = lane >> 2;
    const int t4     = lane & 3;
    const int warp_m = wid >> 2;
    const int warp_n = wid & 3;
    const int row0   = blockIdx.y * 128;
    const int col0   = blockIdx.x * 128;

    float acc[4][4][4];
#pragma unroll
    for (int mt = 0; mt < 4; mt++)
#pragma unroll
        for (int nt = 0; nt < 4; nt++)
#pragma unroll
            for (int q = 0; q < 4; q++) acc[mt][nt][q] = 0.0f;

    const int n_chunks = (K + 31) / 32;
    float4 pa[4];
    uint4  pah[2];
    float4 pb[4];

    auto ldg_chunk = [&](int ch) {
        const int k0 = ch * 32;
        if (AHALF) {
            const __half* A = (const __half*)Av;
#pragma unroll
            for (int t = 0; t < 2; t++) {
                int i  = tid + t * 256;
                int r  = i >> 2, c8 = (i & 3) * 8;
                int gr = row0 + r, gk = k0 + c8;
                if (gr < M && gk + 8 <= K)
                    pah[t] = *reinterpret_cast<const uint4*>(A + (size_t)gr * K + gk);
                else
                    pah[t] = make_uint4(0u, 0u, 0u, 0u);
            }
        } else {
            const float* A = (const float*)Av;
#pragma unroll
            for (int t = 0; t < 4; t++) {
                int i  = tid + t * 256;
                int r  = i >> 3, c4 = (i & 7) * 4;
                int gr = row0 + r, gk = k0 + c4;
                if (gr < M && gk + 4 <= K)
                    pa[t] = *reinterpret_cast<const float4*>(A + (size_t)gr * K + gk);
                else
                    pa[t] = make_float4(0.f, 0.f, 0.f, 0.f);
            }
        }
#pragma unroll
        for (int t = 0; t < 4; t++) {
            int i  = tid + t * 256;
            int r  = i >> 5, c4 = (i & 31) * 4;
            int gk = k0 + r, gn = col0 + c4;
            if (gk < K && gn + 4 <= N)
                pb[t] = *reinterpret_cast<const float4*>(W + (size_t)gk * N + gn);
            else
                pb[t] = make_float4(0.f, 0.f, 0.f, 0.f);
        }
    };

    auto sts_chunk = [&](int st) {
        if (AHALF) {
#pragma unroll
            for (int t = 0; t < 2; t++) {
                int i = tid + t * 256;
                int r = i >> 2, c8 = (i & 3) * 8;
                *reinterpret_cast<uint4*>(smc + (st * STG_BYTES) + r * (ASTRH * 2) + c8 * 2) = pah[t];
            }
        } else {
#pragma unroll
            for (int t = 0; t < 4; t++) {
                int i = tid + t * 256;
                int r = i >> 3, c4 = i & 7;
                uint2 v = make_uint2(packh2(pa[t].x, pa[t].y), packh2(pa[t].z, pa[t].w));
                *reinterpret_cast<uint2*>(smc + (st * STG_BYTES) + r * (ASTRH * 2) + c4 * 8) = v;
            }
        }
#pragma unroll
        for (int t = 0; t < 4; t++) {
            int i = tid + t * 256;
            int r = i >> 5, c4 = i & 31;
            uint2 v = make_uint2(packh2(pb[t].x, pb[t].y), packh2(pb[t].z, pb[t].w));
            *reinterpret_cast<uint2*>(smc + (st * STG_BYTES) + A_BYTES + r * (BSTRH * 2) + c4 * 8) = v;
        }
    };

    auto compute = [&](int st) {
        const uint32_t a_base = sbase + (uint32_t)st * STG_BYTES;
        const uint32_t b_base = a_base + A_BYTES;
#pragma unroll
        for (int ks = 0; ks < 2; ks++) {
            const int kb = ks * 16;
            uint32_t a[4][4], b[4][2];
#pragma unroll
            for (int mt = 0; mt < 4; mt++) {
                uint32_t addr = a_base +
                    (uint32_t)((warp_m * 64 + mt * 16 + (lane & 15)) * ASTRH +
                               kb + ((lane >> 4) << 3)) * 2u;
                asm volatile("ldmatrix.sync.aligned.m8n8.x4.shared.b16 {%0,%1,%2,%3}, [%4];"
                             : "=r"(a[mt][0]), "=r"(a[mt][1]), "=r"(a[mt][2]), "=r"(a[mt][3])
                             : "r"(addr));
            }
#pragma unroll
            for (int nt2 = 0; nt2 < 2; nt2++) {
                uint32_t addr = b_base +
                    (uint32_t)((kb + (lane & 15)) * BSTRH +
                               warp_n * 32 + nt2 * 16 + ((lane >> 4) << 3)) * 2u;
                asm volatile("ldmatrix.sync.aligned.m8n8.x4.trans.shared.b16 {%0,%1,%2,%3}, [%4];"
                             : "=r"(b[nt2 * 2][0]), "=r"(b[nt2 * 2][1]),
                               "=r"(b[nt2 * 2 + 1][0]), "=r"(b[nt2 * 2 + 1][1])
                             : "r"(addr));
            }
#pragma unroll
            for (int mt = 0; mt < 4; mt++)
#pragma unroll
                for (int nt = 0; nt < 4; nt++) {
                    asm volatile(
                        "mma.sync.aligned.m16n8k16.row.col.f32.f16.f16.f32 "
                        "{%0,%1,%2,%3}, {%4,%5,%6,%7}, {%8,%9}, {%0,%1,%2,%3};"
                        : "+f"(acc[mt][nt][0]), "+f"(acc[mt][nt][1]),
                          "+f"(acc[mt][nt][2]), "+f"(acc[mt][nt][3])
                        : "r"(a[mt][0]), "r"(a[mt][1]), "r"(a[mt][2]), "r"(a[mt][3]),
                          "r"(b[nt][0]), "r"(b[nt][1]));
                }
        }
    };

    ldg_chunk(0);
    sts_chunk(0);
    __syncthreads();

    for (int ch = 0; ch < n_chunks; ch++) {
        bool next = (ch + 1 < n_chunks);
        if (next) ldg_chunk(ch + 1);
        compute(ch & 1);
        if (next) {
            sts_chunk((ch + 1) & 1);
            __syncthreads();
        }
    }

    // epilogue
#pragma unroll
    for (int mt = 0; mt < 4; mt++) {
#pragma unroll
        for (int half = 0; half < 2; half++) {
            int gr = row0 + warp_m * 64 + mt * 16 + gid + half * 8;
            if (gr >= M) continue;
#pragma unroll
            for (int nt = 0; nt < 4; nt++) {
                int gc = col0 + warp_n * 32 + nt * 8 + t4 * 2;
                if (gc >= N) continue;
                float2 o;
                o.x = acc[mt][nt][half * 2 + 0];
                o.y = acc[mt][nt][half * 2 + 1];
                if (BIAS) {
                    o.x += __ldg(&bias[gc]);
                    o.y += __ldg(&bias[gc + 1]);
                }
                if (RELU) {
                    o.x = fmaxf(o.x, 0.0f);
                    o.y = fmaxf(o.y, 0.0f);
                }
                if (OUTMODE == 0 || OUTMODE == 2)
                    *reinterpret_cast<float2*>(C + (size_t)gr * N + gc) = o;
                if (OUTMODE >= 1)
                    *reinterpret_cast<__half2*>(C2 + (size_t)gr * N + gc) =
                        __floats2half2_rn(o.x, o.y);
            }
        }
    }
}

// ---------------- edge dtype detection + conversion -------------------------
__global__ void detect_kernel(const int* __restrict__ e_raw, int n_check) {
    __shared__ int nz;
    if (threadIdx.x == 0) nz = 0;
    __syncthreads();
    for (int i = threadIdx.x; i < n_check; i += blockDim.x)
        if (e_raw[2 * i + 1] != 0) atomicAdd(&nz, 1);
    __syncthreads();
    if (threadIdx.x == 0) g_is64 = (nz == 0) ? 1 : 0;
}

__global__ void convert_count_kernel(const int* __restrict__ e_raw,
                                     int* __restrict__ src32, int* __restrict__ dst32,
                                     int* __restrict__ cnt, int* __restrict__ fill, int E) {
    int i = blockIdx.x * blockDim.x + threadIdx.x;
    if (i < N_NODES) { cnt[i] = 0; fill[i] = 0; }
    if (i >= E) return;
    int s, d;
    if (g_is64) { s = e_raw[2 * i]; d = e_raw[2 * (E + i)]; }
    else        { s = e_raw[i];     d = e_raw[E + i]; }
    src32[i] = s;
    dst32[i] = d;
    atomicAdd(&cnt[d], 1);
}

__global__ void norm_kernel(const int* __restrict__ cnt,
                            float* __restrict__ dinv, float* __restrict__ selfw, int n) {
    int i = blockIdx.x * blockDim.x + threadIdx.x;
    if (i < n) {
        float d = (float)cnt[i] + 1.0f;
        dinv[i]  = rsqrtf(d);
        selfw[i] = 1.0f / d;
    }
}

// ---------------- exclusive scan of cnt -> ptr ------------------------------
__global__ void scan1_kernel(const int* __restrict__ cnt, int* __restrict__ ptr,
                             int* __restrict__ bsum, int n) {
    __shared__ int sh[SCAN_B];
    int b = blockIdx.x;
    int i = b * SCAN_B + threadIdx.x;
    int v = (i < n) ? cnt[i] : 0;
    sh[threadIdx.x] = v;
    __syncthreads();
    for (int off = 1; off < SCAN_B; off <<= 1) {
        int t = (threadIdx.x >= off) ? sh[threadIdx.x - off] : 0;
        __syncthreads();
        sh[threadIdx.x] += t;
        __syncthreads();
    }
    if (i < n) ptr[i] = sh[threadIdx.x] - v;
    if (threadIdx.x == SCAN_B - 1) bsum[b] = sh[SCAN_B - 1];
}

__global__ void scan2_kernel(int* __restrict__ bsum, int nb) {
    __shared__ int sh[256];
    int v = (threadIdx.x < nb) ? bsum[threadIdx.x] : 0;
    sh[threadIdx.x] = v;
    __syncthreads();
    for (int off = 1; off < 256; off <<= 1) {
        int t = (threadIdx.x >= off) ? sh[threadIdx.x - off] : 0;
        __syncthreads();
        sh[threadIdx.x] += t;
        __syncthreads();
    }
    if (threadIdx.x < nb) bsum[threadIdx.x] = sh[threadIdx.x] - v;
}

__global__ void scan3_kernel(int* __restrict__ ptr, const int* __restrict__ bsum,
                             int n, int E) {
    int i = blockIdx.x * SCAN_B + threadIdx.x;
    if (i < n) ptr[i] += bsum[blockIdx.x];
    if (i == n) ptr[n] = E;
}

__global__ void csr_fill_kernel(const int* __restrict__ src, const int* __restrict__ dst,
                                const int* __restrict__ ptr, int* __restrict__ fill,
                                int* __restrict__ csr_src, int E) {
    int i = blockIdx.x * blockDim.x + threadIdx.x;
    if (i >= E) return;
    int s = src[i], d = dst[i];
    int pos = atomicAdd(&fill[d], 1);
    csr_src[ptr[d] + pos] = s;
}

// ---------------- fused aggregation + BN + ReLU + residual ------------------
__global__ void agg_kernel(const int* __restrict__ ptr,
                           const int* __restrict__ csr_src,
                           const float* __restrict__ dinv,
                           const float* __restrict__ selfw,
                           const __half* __restrict__ hw,
                           const float* __restrict__ cb,
                           const float* __restrict__ gamma,
                           const float* __restrict__ beta,
                           float* __restrict__ h,
                           __half* __restrict__ h16, int N)
{
    int d = blockIdx.x * 8 + (threadIdx.x >> 5);
    if (d >= N) return;
    int lane = threadIdx.x & 31;

    float acc[8];
#pragma unroll
    for (int q = 0; q < 8; q++) acc[q] = 0.0f;

    float dv_d = __ldg(&dinv[d]);
    int beg = __ldg(&ptr[d]);
    int end = __ldg(&ptr[d + 1]);
    int j = beg;
    for (; j + 4 <= end; j += 4) {
        int s0 = __ldg(&csr_src[j]);
        int s1 = __ldg(&csr_src[j + 1]);
        int s2 = __ldg(&csr_src[j + 2]);
        int s3 = __ldg(&csr_src[j + 3]);
        float w0 = __ldg(&dinv[s0]) * dv_d;
        float w1 = __ldg(&dinv[s1]) * dv_d;
        float w2 = __ldg(&dinv[s2]) * dv_d;
        float w3 = __ldg(&dinv[s3]) * dv_d;
        uint4 v0 = __ldg(reinterpret_cast<const uint4*>(hw + (size_t)s0 * HID) + lane);
        uint4 v1 = __ldg(reinterpret_cast<const uint4*>(hw + (size_t)s1 * HID) + lane);
        uint4 v2 = __ldg(reinterpret_cast<const uint4*>(hw + (size_t)s2 * HID) + lane);
        uint4 v3 = __ldg(reinterpret_cast<const uint4*>(hw + (size_t)s3 * HID) + lane);
        const __half2* p0 = reinterpret_cast<const __half2*>(&v0);
        const __half2* p1 = reinterpret_cast<const __half2*>(&v1);
        const __half2* p2 = reinterpret_cast<const __half2*>(&v2);
        const __half2* p3 = reinterpret_cast<const __half2*>(&v3);
#pragma unroll
        for (int q = 0; q < 4; q++) {
            float2 f0 = __half22float2(p0[q]);
            float2 f1 = __half22float2(p1[q]);
            float2 f2 = __half22float2(p2[q]);
            float2 f3 = __half22float2(p3[q]);
            acc[2 * q]     += f0.x * w0 + f1.x * w1 + f2.x * w2 + f3.x * w3;
            acc[2 * q + 1] += f0.y * w0 + f1.y * w1 + f2.y * w2 + f3.y * w3;
        }
    }
    for (; j < end; j++) {
        int s = __ldg(&csr_src[j]);
        float w = __ldg(&dinv[s]) * dv_d;
        uint4 v = __ldg(reinterpret_cast<const uint4*>(hw + (size_t)s * HID) + lane);
        const __half2* p = reinterpret_cast<const __half2*>(&v);
#pragma unroll
        for (int q = 0; q < 4; q++) {
            float2 f = __half22float2(p[q]);
            acc[2 * q]     = fmaf(f.x, w, acc[2 * q]);
            acc[2 * q + 1] = fmaf(f.y, w, acc[2 * q + 1]);
        }
    }

    float sw = __ldg(&selfw[d]);
    uint4 v = __ldg(reinterpret_cast<const uint4*>(hw + (size_t)d * HID) + lane);
    const __half2* p = reinterpret_cast<const __half2*>(&v);
#pragma unroll
    for (int q = 0; q < 4; q++) {
        float2 f = __half22float2(p[q]);
        acc[2 * q]     = fmaf(f.x, sw, acc[2 * q]);
        acc[2 * q + 1] = fmaf(f.y, sw, acc[2 * q + 1]);
    }

    const float4* cb4 = reinterpret_cast<const float4*>(cb);
    const float4* g4  = reinterpret_cast<const float4*>(gamma);
    const float4* bt4 = reinterpret_cast<const float4*>(beta);
    float4* hrow = reinterpret_cast<float4*>(h + (size_t)d * HID);

    uint32_t o16[4];
#pragma unroll
    for (int q2 = 0; q2 < 2; q2++) {
        int c4i = lane * 2 + q2;
        float4 b  = __ldg(&cb4[c4i]);
        float4 g  = __ldg(&g4[c4i]);
        float4 bt = __ldg(&bt4[c4i]);
        float4 hv = hrow[c4i];
        hv.x += fmaxf(fmaf(acc[q2 * 4 + 0] + b.x, g.x, bt.x), 0.0f);
        hv.y += fmaxf(fmaf(acc[q2 * 4 + 1] + b.y, g.y, bt.y), 0.0f);
        hv.z += fmaxf(fmaf(acc[q2 * 4 + 2] + b.z, g.z, bt.z), 0.0f);
        hv.w += fmaxf(fmaf(acc[q2 * 4 + 3] + b.w, g.w, bt.w), 0.0f);
        hrow[c4i] = hv;
        o16[q2 * 2]     = packh2(hv.x, hv.y);
        o16[q2 * 2 + 1] = packh2(hv.z, hv.w);
    }
    *reinterpret_cast<uint4*>(h16 + (size_t)d * HID + 8 * lane) =
        make_uint4(o16[0], o16[1], o16[2], o16[3]);
}

// ---------------- fused classifier tail: c2 -> relu -> c3 -> out ------------
__global__ void __launch_bounds__(256) cls_tail_kernel(
    const float* __restrict__ c2in,
    const float* __restrict__ W2, const float* __restrict__ b2,
    const float* __restrict__ W3, const float* __restrict__ b3,
    float* __restrict__ out, int N)
{
    __shared__ float sW2[64 * 32];
    __shared__ float sW3[32 * 40];
    __shared__ float sb2[32];
    __shared__ float sb3[40];
    for (int i = threadIdx.x; i < 64 * 32; i += 256) sW2[i] = W2[i];
    for (int i = threadIdx.x; i < 32 * 40; i += 256) sW3[i] = W3[i];
    if (threadIdx.x < 32) sb2[threadIdx.x] = b2[threadIdx.x];
    if (threadIdx.x < 40) sb3[threadIdx.x] = b3[threadIdx.x];
    __syncthreads();

    int r = blockIdx.x * 256 + threadIdx.x;
    if (r >= N) return;

    float x[64];
    const float4* row = reinterpret_cast<const float4*>(c2in + (size_t)r * 64);
#pragma unroll
    for (int q = 0; q < 16; q++) {
        float4 v = __ldg(&row[q]);
        x[4 * q] = v.x; x[4 * q + 1] = v.y; x[4 * q + 2] = v.z; x[4 * q + 3] = v.w;
    }

    float h2[32];
#pragma unroll
    for (int n = 0; n < 32; n++) h2[n] = sb2[n];
#pragma unroll 8
    for (int k = 0; k < 64; k++) {
        float xk = x[k];
#pragma unroll
        for (int n = 0; n < 32; n++)
            h2[n] = fmaf(xk, sW2[k * 32 + n], h2[n]);
    }
#pragma unroll
    for (int n = 0; n < 32; n++) h2[n] = fmaxf(h2[n], 0.0f);

    float* orow = out + (size_t)r * 40;
#pragma unroll
    for (int n = 0; n < 40; n++) {
        float o = sb3[n];
#pragma unroll
        for (int k = 0; k < 32; k++)
            o = fmaf(h2[k], sW3[k * 40 + n], o);
        orow[n] = o;
    }
}

// ---------------- host launcher ---------------------------------------------
template<int OUTMODE, bool BIAS, bool RELU, bool AHALF>
static void launch_mma_gemm(const void* A, const float* W, const float* bias,
                            float* C, __half* C2, int M, int N, int K) {
    cudaFuncSetAttribute(mma_gemm_kernel<OUTMODE, BIAS, RELU, AHALF>,
                         cudaFuncAttributeMaxDynamicSharedMemorySize, MMA_SMEM);
    dim3 grid((N + 127) / 128, (M + 127) / 128);
    mma_gemm_kernel<OUTMODE, BIAS, RELU, AHALF><<<grid, 256, MMA_SMEM>>>(A, W, bias, C, C2, M, N, K);
}

extern "C" void kernel_launch(void* const* d_in, const int* in_sizes, int n_in,
                              void* d_out, int out_size)
{
    const float* x      = (const float*)d_in[0];
    const int*   e_raw  = (const int*)d_in[1];
    const float* embW   = (const float*)d_in[2];
    const float* embB   = (const float*)d_in[3];
    const float* convW  = (const float*)d_in[4];
    const float* convB  = (const float*)d_in[5];
    const float* gamma  = (const float*)d_in[6];
    const float* beta   = (const float*)d_in[7];
    const float* W0 = (const float*)d_in[8];
    const float* b0 = (const float*)d_in[9];
    const float* W1 = (const float*)d_in[10];
    const float* b1 = (const float*)d_in[11];
    const float* W2 = (const float*)d_in[12];
    const float* b2 = (const float*)d_in[13];
    const float* W3 = (const float*)d_in[14];
    const float* b3 = (const float*)d_in[15];
    float* out = (float*)d_out;

    const int N = N_NODES;
    const int E = in_sizes[1] / 2;

    float *h, *dinv, *selfw, *c2;
    __half *hw, *h16, *c1;
    int *src32, *dst32, *cnt, *ptr, *fill, *csr_src, *bsum;
    cudaGetSymbolAddress((void**)&h,       g_h);
    cudaGetSymbolAddress((void**)&h16,     g_h16);
    cudaGetSymbolAddress((void**)&hw,      g_hw);
    cudaGetSymbolAddress((void**)&dinv,    g_dinv);
    cudaGetSymbolAddress((void**)&selfw,   g_self);
    cudaGetSymbolAddress((void**)&c1,      g_c1);
    cudaGetSymbolAddress((void**)&c2,      g_c2);
    cudaGetSymbolAddress((void**)&src32,   g_src32);
    cudaGetSymbolAddress((void**)&dst32,   g_dst32);
    cudaGetSymbolAddress((void**)&cnt,     g_cnt);
    cudaGetSymbolAddress((void**)&ptr,     g_ptr);
    cudaGetSymbolAddress((void**)&fill,    g_fill);
    cudaGetSymbolAddress((void**)&csr_src, g_csr_src);
    cudaGetSymbolAddress((void**)&bsum,    g_bsum);

    int nb = (N + SCAN_B - 1) / SCAN_B;

    // Fork a side stream for the CSR-prep chain; it is independent of the
    // embed + conv1 GEMMs. Stream/events are host handles (no device memory);
    // kernel_launch only runs a few times (graph replays skip host code).
    cudaStream_t s2;
    cudaEvent_t ev_fork, ev_prep;
    cudaStreamCreateWithFlags(&s2, cudaStreamNonBlocking);
    cudaEventCreateWithFlags(&ev_fork, cudaEventDisableTiming);
    cudaEventCreateWithFlags(&ev_prep, cudaEventDisableTiming);

    cudaEventRecord(ev_fork, 0);
    cudaStreamWaitEvent(s2, ev_fork, 0);

    // side stream: edge prep + CSR build
    detect_kernel<<<1, 256, 0, s2>>>(e_raw, 1024);
    convert_count_kernel<<<(E + 255) / 256, 256, 0, s2>>>(e_raw, src32, dst32, cnt, fill, E);
    norm_kernel<<<(N + 255) / 256, 256, 0, s2>>>(cnt, dinv, selfw, N);
    scan1_kernel<<<nb, SCAN_B, 0, s2>>>(cnt, ptr, bsum, N);
    scan2_kernel<<<1, 256, 0, s2>>>(bsum, nb);
    scan3_kernel<<<nb + 1, SCAN_B, 0, s2>>>(ptr, bsum, N, E);
    csr_fill_kernel<<<(E + 255) / 256, 256, 0, s2>>>(src32, dst32, ptr, fill, csr_src, E);
    cudaEventRecord(ev_prep, s2);

    // main stream: embed GEMM + conv1 GEMM (independent of CSR)
    launch_mma_gemm<2, true, false, false>(x, embW, embB, h, h16, N, HID, 500);
    launch_mma_gemm<1, false, false, true>(h16, convW, nullptr, nullptr, hw, N, HID, HID);

    // join: aggregation needs the CSR
    cudaStreamWaitEvent(0, ev_prep, 0);

    const int agg_blocks = (N + 7) / 8;
    for (int l = 0; l < 3; l++) {
        const float* cbl = convB + (size_t)l * HID;
        const float* gl  = gamma + (size_t)l * HID;
        const float* btl = beta  + (size_t)l * HID;

        agg_kernel<<<agg_blocks, 256>>>(ptr, csr_src, dinv, selfw, hw, cbl, gl, btl, h, h16, N);
        if (l + 1 < 3) {
            const float* Wn = convW + (size_t)(l + 1) * HID * HID;
            launch_mma_gemm<1, false, false, true>(h16, Wn, nullptr, nullptr, hw, N, HID, HID);
        }
    }

    // classifier MLP
    launch_mma_gemm<1, true, true, true>(h16, W0, b0, nullptr, c1, N, 128, 256);
    launch_mma_gemm<0, true, true, true>(c1, W1, b1, c2, nullptr, N, 64, 128);
    cls_tail_kernel<<<(N + 255) / 256, 256>>>(c2, W2, b2, W3, b3, out, N);
}

// round 16
// speedup vs baseline: 1.3361x; 1.0049x over previous
#include <cuda_runtime.h>
#include <cuda_fp16.h>
#include <stdint.h>

#define N_NODES 100000
#define N_EDGES 1600000
#define HID 256
#define SCAN_B 1024

// ---------------- scratch (device globals; no allocation allowed) ----------
__device__ __half g_h16[(size_t)N_NODES * HID];   // residual state (fp16)
__device__ __half g_hw[(size_t)N_NODES * HID];
__device__ float  g_dinv[N_NODES];
__device__ float  g_self[N_NODES];
__device__ __half g_c1[(size_t)N_NODES * 128];
__device__ float  g_c2[(size_t)N_NODES * 64];
__device__ int    g_src32[N_EDGES];
__device__ int    g_dst32[N_EDGES];
__device__ int    g_cnt[N_NODES];
__device__ int    g_ptr[N_NODES + 1];
__device__ int    g_fill[N_NODES];
__device__ int    g_csr_src[N_EDGES];
__device__ int    g_bsum[(N_NODES + SCAN_B - 1) / SCAN_B + 1];
__device__ int    g_is64;

__device__ __forceinline__ uint32_t smem_u32(const void* p) {
    uint32_t a;
    asm("{ .reg .u64 t; cvta.to.shared.u64 t, %1; cvt.u32.u64 %0, t; }" : "=r"(a) : "l"(p));
    return a;
}
__device__ __forceinline__ uint32_t packh2(float lo, float hi) {
    uint32_t o;
    asm("cvt.rn.f16x2.f32 %0, %1, %2;" : "=r"(o) : "f"(hi), "f"(lo));
    return o;
}

// ====== fp16 mma m16n8k16 GEMM with ldmatrix fragments =======================
#define ASTRH 40
#define BSTRH 136
#define A_BYTES (128 * ASTRH * 2)
#define B_BYTES (32 * BSTRH * 2)
#define STG_BYTES (A_BYTES + B_BYTES)
#define MMA_SMEM (2 * STG_BYTES)

template<int OUTMODE, bool BIAS, bool RELU, bool AHALF>
__global__ void __launch_bounds__(256, 2) mma_gemm_kernel(
    const void* __restrict__ Av, const float* __restrict__ W,
    const float* __restrict__ bias,
    float* __restrict__ C, __half* __restrict__ C2,
    int M, int N, int K)
{
    extern __shared__ char smc[];
    const uint32_t sbase = smem_u32(smc);

    const int tid    = threadIdx.x;
    const int wid    = tid >> 5;
    const int lane   = tid & 31;
    const int gid    = lane >> 2;
    const int t4     = lane & 3;
    const int warp_m = wid >> 2;
    const int warp_n = wid & 3;
    const int row0   = blockIdx.y * 128;
    const int col0   = blockIdx.x * 128;

    float acc[4][4][4];
#pragma unroll
    for (int mt = 0; mt < 4; mt++)
#pragma unroll
        for (int nt = 0; nt < 4; nt++)
#pragma unroll
            for (int q = 0; q < 4; q++) acc[mt][nt][q] = 0.0f;

    const int n_chunks = (K + 31) / 32;
    float4 pa[4];
    uint4  pah[2];
    float4 pb[4];

    auto ldg_chunk = [&](int ch) {
        const int k0 = ch * 32;
        if (AHALF) {
            const __half* A = (const __half*)Av;
#pragma unroll
            for (int t = 0; t < 2; t++) {
                int i  = tid + t * 256;
                int r  = i >> 2, c8 = (i & 3) * 8;
                int gr = row0 + r, gk = k0 + c8;
                if (gr < M && gk + 8 <= K)
                    pah[t] = *reinterpret_cast<const uint4*>(A + (size_t)gr * K + gk);
                else
                    pah[t] = make_uint4(0u, 0u, 0u, 0u);
            }
        } else {
            const float* A = (const float*)Av;
#pragma unroll
            for (int t = 0; t < 4; t++) {
                int i  = tid + t * 256;
                int r  = i >> 3, c4 = (i & 7) * 4;
                int gr = row0 + r, gk = k0 + c4;
                if (gr < M && gk + 4 <= K)
                    pa[t] = *reinterpret_cast<const float4*>(A + (size_t)gr * K + gk);
                else
                    pa[t] = make_float4(0.f, 0.f, 0.f, 0.f);
            }
        }
#pragma unroll
        for (int t = 0; t < 4; t++) {
            int i  = tid + t * 256;
            int r  = i >> 5, c4 = (i & 31) * 4;
            int gk = k0 + r, gn = col0 + c4;
            if (gk < K && gn + 4 <= N)
                pb[t] = *reinterpret_cast<const float4*>(W + (size_t)gk * N + gn);
            else
                pb[t] = make_float4(0.f, 0.f, 0.f, 0.f);
        }
    };

    auto sts_chunk = [&](int st) {
        if (AHALF) {
#pragma unroll
            for (int t = 0; t < 2; t++) {
                int i = tid + t * 256;
                int r = i >> 2, c8 = (i & 3) * 8;
                *reinterpret_cast<uint4*>(smc + (st * STG_BYTES) + r * (ASTRH * 2) + c8 * 2) = pah[t];
            }
        } else {
#pragma unroll
            for (int t = 0; t < 4; t++) {
                int i = tid + t * 256;
                int r = i >> 3, c4 = i & 7;
                uint2 v = make_uint2(packh2(pa[t].x, pa[t].y), packh2(pa[t].z, pa[t].w));
                *reinterpret_cast<uint2*>(smc + (st * STG_BYTES) + r * (ASTRH * 2) + c4 * 8) = v;
            }
        }
#pragma unroll
        for (int t = 0; t < 4; t++) {
            int i = tid + t * 256;
            int r = i >> 5, c4 = i & 31;
            uint2 v = make_uint2(packh2(pb[t].x, pb[t].y), packh2(pb[t].z, pb[t].w));
            *reinterpret_cast<uint2*>(smc + (st * STG_BYTES) + A_BYTES + r * (BSTRH * 2) + c4 * 8) = v;
        }
    };

    auto compute = [&](int st) {
        const uint32_t a_base = sbase + (uint32_t)st * STG_BYTES;
        const uint32_t b_base = a_base + A_BYTES;
#pragma unroll
        for (int ks = 0; ks < 2; ks++) {
            const int kb = ks * 16;
            uint32_t a[4][4], b[4][2];
#pragma unroll
            for (int mt = 0; mt < 4; mt++) {
                uint32_t addr = a_base +
                    (uint32_t)((warp_m * 64 + mt * 16 + (lane & 15)) * ASTRH +
                               kb + ((lane >> 4) << 3)) * 2u;
                asm volatile("ldmatrix.sync.aligned.m8n8.x4.shared.b16 {%0,%1,%2,%3}, [%4];"
                             : "=r"(a[mt][0]), "=r"(a[mt][1]), "=r"(a[mt][2]), "=r"(a[mt][3])
                             : "r"(addr));
            }
#pragma unroll
            for (int nt2 = 0; nt2 < 2; nt2++) {
                uint32_t addr = b_base +
                    (uint32_t)((kb + (lane & 15)) * BSTRH +
                               warp_n * 32 + nt2 * 16 + ((lane >> 4) << 3)) * 2u;
                asm volatile("ldmatrix.sync.aligned.m8n8.x4.trans.shared.b16 {%0,%1,%2,%3}, [%4];"
                             : "=r"(b[nt2 * 2][0]), "=r"(b[nt2 * 2][1]),
                               "=r"(b[nt2 * 2 + 1][0]), "=r"(b[nt2 * 2 + 1][1])
                             : "r"(addr));
            }
#pragma unroll
            for (int mt = 0; mt < 4; mt++)
#pragma unroll
                for (int nt = 0; nt < 4; nt++) {
                    asm volatile(
                        "mma.sync.aligned.m16n8k16.row.col.f32.f16.f16.f32 "
                        "{%0,%1,%2,%3}, {%4,%5,%6,%7}, {%8,%9}, {%0,%1,%2,%3};"
                        : "+f"(acc[mt][nt][0]), "+f"(acc[mt][nt][1]),
                          "+f"(acc[mt][nt][2]), "+f"(acc[mt][nt][3])
                        : "r"(a[mt][0]), "r"(a[mt][1]), "r"(a[mt][2]), "r"(a[mt][3]),
                          "r"(b[nt][0]), "r"(b[nt][1]));
                }
        }
    };

    ldg_chunk(0);
    sts_chunk(0);
    __syncthreads();

    for (int ch = 0; ch < n_chunks; ch++) {
        bool next = (ch + 1 < n_chunks);
        if (next) ldg_chunk(ch + 1);
        compute(ch & 1);
        if (next) {
            sts_chunk((ch + 1) & 1);
            __syncthreads();
        }
    }

    // epilogue
#pragma unroll
    for (int mt = 0; mt < 4; mt++) {
#pragma unroll
        for (int half = 0; half < 2; half++) {
            int gr = row0 + warp_m * 64 + mt * 16 + gid + half * 8;
            if (gr >= M) continue;
#pragma unroll
            for (int nt = 0; nt < 4; nt++) {
                int gc = col0 + warp_n * 32 + nt * 8 + t4 * 2;
                if (gc >= N) continue;
                float2 o;
                o.x = acc[mt][nt][half * 2 + 0];
                o.y = acc[mt][nt][half * 2 + 1];
                if (BIAS) {
                    o.x += __ldg(&bias[gc]);
                    o.y += __ldg(&bias[gc + 1]);
                }
                if (RELU) {
                    o.x = fmaxf(o.x, 0.0f);
                    o.y = fmaxf(o.y, 0.0f);
                }
                if (OUTMODE == 0 || OUTMODE == 2)
                    *reinterpret_cast<float2*>(C + (size_t)gr * N + gc) = o;
                if (OUTMODE >= 1)
                    *reinterpret_cast<__half2*>(C2 + (size_t)gr * N + gc) =
                        __floats2half2_rn(o.x, o.y);
            }
        }
    }
}

// ---------------- prep kernels ----------------------------------------------
__global__ void zero_kernel(int* __restrict__ cnt, int* __restrict__ fill, int n) {
    int i = blockIdx.x * blockDim.x + threadIdx.x;
    if (i < n) { cnt[i] = 0; fill[i] = 0; }
}

__global__ void detect_kernel(const int* __restrict__ e_raw, int n_check) {
    __shared__ int nz;
    if (threadIdx.x == 0) nz = 0;
    __syncthreads();
    for (int i = threadIdx.x; i < n_check; i += blockDim.x)
        if (e_raw[2 * i + 1] != 0) atomicAdd(&nz, 1);
    __syncthreads();
    if (threadIdx.x == 0) g_is64 = (nz == 0) ? 1 : 0;
}

__global__ void convert_count_kernel(const int* __restrict__ e_raw,
                                     int* __restrict__ src32, int* __restrict__ dst32,
                                     int* __restrict__ cnt, int E) {
    int i = blockIdx.x * blockDim.x + threadIdx.x;
    if (i >= E) return;
    int s, d;
    if (g_is64) { s = e_raw[2 * i]; d = e_raw[2 * (E + i)]; }
    else        { s = e_raw[i];     d = e_raw[E + i]; }
    src32[i] = s;
    dst32[i] = d;
    atomicAdd(&cnt[d], 1);
}

__global__ void norm_kernel(const int* __restrict__ cnt,
                            float* __restrict__ dinv, float* __restrict__ selfw, int n) {
    int i = blockIdx.x * blockDim.x + threadIdx.x;
    if (i < n) {
        float d = (float)cnt[i] + 1.0f;
        dinv[i]  = rsqrtf(d);
        selfw[i] = 1.0f / d;
    }
}

__global__ void scan1_kernel(const int* __restrict__ cnt, int* __restrict__ ptr,
                             int* __restrict__ bsum, int n) {
    __shared__ int sh[SCAN_B];
    int b = blockIdx.x;
    int i = b * SCAN_B + threadIdx.x;
    int v = (i < n) ? cnt[i] : 0;
    sh[threadIdx.x] = v;
    __syncthreads();
    for (int off = 1; off < SCAN_B; off <<= 1) {
        int t = (threadIdx.x >= off) ? sh[threadIdx.x - off] : 0;
        __syncthreads();
        sh[threadIdx.x] += t;
        __syncthreads();
    }
    if (i < n) ptr[i] = sh[threadIdx.x] - v;
    if (threadIdx.x == SCAN_B - 1) bsum[b] = sh[SCAN_B - 1];
}

__global__ void scan2_kernel(int* __restrict__ bsum, int nb) {
    __shared__ int sh[256];
    int v = (threadIdx.x < nb) ? bsum[threadIdx.x] : 0;
    sh[threadIdx.x] = v;
    __syncthreads();
    for (int off = 1; off < 256; off <<= 1) {
        int t = (threadIdx.x >= off) ? sh[threadIdx.x - off] : 0;
        __syncthreads();
        sh[threadIdx.x] += t;
        __syncthreads();
    }
    if (threadIdx.x < nb) bsum[threadIdx.x] = sh[threadIdx.x] - v;
}

__global__ void scan3_kernel(int* __restrict__ ptr, const int* __restrict__ bsum,
                             int n, int E) {
    int i = blockIdx.x * SCAN_B + threadIdx.x;
    if (i < n) ptr[i] += bsum[blockIdx.x];
    if (i == n) ptr[n] = E;
}

__global__ void csr_fill_kernel(const int* __restrict__ src, const int* __restrict__ dst,
                                const int* __restrict__ ptr, int* __restrict__ fill,
                                int* __restrict__ csr_src, int E) {
    int i = blockIdx.x * blockDim.x + threadIdx.x;
    if (i >= E) return;
    int s = src[i], d = dst[i];
    int pos = atomicAdd(&fill[d], 1);
    csr_src[ptr[d] + pos] = s;
}

// canonicalize: sort each adjacency segment -> bitwise-deterministic sums
__global__ void sort_csr_kernel(const int* __restrict__ ptr,
                                int* __restrict__ csr_src, int N) {
    int d = blockIdx.x * blockDim.x + threadIdx.x;
    if (d >= N) return;
    int beg = ptr[d], end = ptr[d + 1];
    for (int i = beg + 1; i < end; i++) {
        int key = csr_src[i];
        int j = i - 1;
        while (j >= beg && csr_src[j] > key) {
            csr_src[j + 1] = csr_src[j];
            j--;
        }
        csr_src[j + 1] = key;
    }
}

// ---------------- fused aggregation + BN + ReLU + residual (fp16 state) -----
__global__ void agg_kernel(const int* __restrict__ ptr,
                           const int* __restrict__ csr_src,
                           const float* __restrict__ dinv,
                           const float* __restrict__ selfw,
                           const __half* __restrict__ hw,
                           const float* __restrict__ cb,
                           const float* __restrict__ gamma,
                           const float* __restrict__ beta,
                           __half* __restrict__ h16, int N)
{
    int d = blockIdx.x * 8 + (threadIdx.x >> 5);
    if (d >= N) return;
    int lane = threadIdx.x & 31;

    float acc[8];
#pragma unroll
    for (int q = 0; q < 8; q++) acc[q] = 0.0f;

    float dv_d = __ldg(&dinv[d]);
    int beg = __ldg(&ptr[d]);
    int end = __ldg(&ptr[d + 1]);
    int j = beg;
    for (; j + 4 <= end; j += 4) {
        int s0 = __ldg(&csr_src[j]);
        int s1 = __ldg(&csr_src[j + 1]);
        int s2 = __ldg(&csr_src[j + 2]);
        int s3 = __ldg(&csr_src[j + 3]);
        float w0 = __ldg(&dinv[s0]) * dv_d;
        float w1 = __ldg(&dinv[s1]) * dv_d;
        float w2 = __ldg(&dinv[s2]) * dv_d;
        float w3 = __ldg(&dinv[s3]) * dv_d;
        uint4 v0 = __ldg(reinterpret_cast<const uint4*>(hw + (size_t)s0 * HID) + lane);
        uint4 v1 = __ldg(reinterpret_cast<const uint4*>(hw + (size_t)s1 * HID) + lane);
        uint4 v2 = __ldg(reinterpret_cast<const uint4*>(hw + (size_t)s2 * HID) + lane);
        uint4 v3 = __ldg(reinterpret_cast<const uint4*>(hw + (size_t)s3 * HID) + lane);
        const __half2* p0 = reinterpret_cast<const __half2*>(&v0);
        const __half2* p1 = reinterpret_cast<const __half2*>(&v1);
        const __half2* p2 = reinterpret_cast<const __half2*>(&v2);
        const __half2* p3 = reinterpret_cast<const __half2*>(&v3);
#pragma unroll
        for (int q = 0; q < 4; q++) {
            float2 f0 = __half22float2(p0[q]);
            float2 f1 = __half22float2(p1[q]);
            float2 f2 = __half22float2(p2[q]);
            float2 f3 = __half22float2(p3[q]);
            acc[2 * q]     += f0.x * w0 + f1.x * w1 + f2.x * w2 + f3.x * w3;
            acc[2 * q + 1] += f0.y * w0 + f1.y * w1 + f2.y * w2 + f3.y * w3;
        }
    }
    for (; j < end; j++) {
        int s = __ldg(&csr_src[j]);
        float w = __ldg(&dinv[s]) * dv_d;
        uint4 v = __ldg(reinterpret_cast<const uint4*>(hw + (size_t)s * HID) + lane);
        const __half2* p = reinterpret_cast<const __half2*>(&v);
#pragma unroll
        for (int q = 0; q < 4; q++) {
            float2 f = __half22float2(p[q]);
            acc[2 * q]     = fmaf(f.x, w, acc[2 * q]);
            acc[2 * q + 1] = fmaf(f.y, w, acc[2 * q + 1]);
        }
    }

    float sw = __ldg(&selfw[d]);
    uint4 v = __ldg(reinterpret_cast<const uint4*>(hw + (size_t)d * HID) + lane);
    const __half2* p = reinterpret_cast<const __half2*>(&v);
#pragma unroll
    for (int q = 0; q < 4; q++) {
        float2 f = __half22float2(p[q]);
        acc[2 * q]     = fmaf(f.x, sw, acc[2 * q]);
        acc[2 * q + 1] = fmaf(f.y, sw, acc[2 * q + 1]);
    }

    const float4* cb4 = reinterpret_cast<const float4*>(cb);
    const float4* g4  = reinterpret_cast<const float4*>(gamma);
    const float4* bt4 = reinterpret_cast<const float4*>(beta);
    uint4* hrow16 = reinterpret_cast<uint4*>(h16 + (size_t)d * HID) + lane;

    uint4 hv16 = *hrow16;
    const __half2* hp = reinterpret_cast<const __half2*>(&hv16);
    uint32_t o16[4];
#pragma unroll
    for (int q2 = 0; q2 < 2; q2++) {
        int c4i = lane * 2 + q2;
        float4 b  = __ldg(&cb4[c4i]);
        float4 g  = __ldg(&g4[c4i]);
        float4 bt = __ldg(&bt4[c4i]);
        float2 h0 = __half22float2(hp[q2 * 2]);
        float2 h1 = __half22float2(hp[q2 * 2 + 1]);
        float r0 = h0.x + fmaxf(fmaf(acc[q2 * 4 + 0] + b.x, g.x, bt.x), 0.0f);
        float r1 = h0.y + fmaxf(fmaf(acc[q2 * 4 + 1] + b.y, g.y, bt.y), 0.0f);
        float r2 = h1.x + fmaxf(fmaf(acc[q2 * 4 + 2] + b.z, g.z, bt.z), 0.0f);
        float r3 = h1.y + fmaxf(fmaf(acc[q2 * 4 + 3] + b.w, g.w, bt.w), 0.0f);
        o16[q2 * 2]     = packh2(r0, r1);
        o16[q2 * 2 + 1] = packh2(r2, r3);
    }
    *hrow16 = make_uint4(o16[0], o16[1], o16[2], o16[3]);
}

// ---------------- fused classifier tail: c2 -> relu -> c3 -> out ------------
__global__ void __launch_bounds__(256) cls_tail_kernel(
    const float* __restrict__ c2in,
    const float* __restrict__ W2, const float* __restrict__ b2,
    const float* __restrict__ W3, const float* __restrict__ b3,
    float* __restrict__ out, int N)
{
    __shared__ float sW2[64 * 32];
    __shared__ float sW3[32 * 40];
    __shared__ float sb2[32];
    __shared__ float sb3[40];
    for (int i = threadIdx.x; i < 64 * 32; i += 256) sW2[i] = W2[i];
    for (int i = threadIdx.x; i < 32 * 40; i += 256) sW3[i] = W3[i];
    if (threadIdx.x < 32) sb2[threadIdx.x] = b2[threadIdx.x];
    if (threadIdx.x < 40) sb3[threadIdx.x] = b3[threadIdx.x];
    __syncthreads();

    int r = blockIdx.x * 256 + threadIdx.x;
    if (r >= N) return;

    float x[64];
    const float4* row = reinterpret_cast<const float4*>(c2in + (size_t)r * 64);
#pragma unroll
    for (int q = 0; q < 16; q++) {
        float4 v = __ldg(&row[q]);
        x[4 * q] = v.x; x[4 * q + 1] = v.y; x[4 * q + 2] = v.z; x[4 * q + 3] = v.w;
    }

    float h2[32];
#pragma unroll
    for (int n = 0; n < 32; n++) h2[n] = sb2[n];
#pragma unroll 8
    for (int k = 0; k < 64; k++) {
        float xk = x[k];
#pragma unroll
        for (int n = 0; n < 32; n++)
            h2[n] = fmaf(xk, sW2[k * 32 + n], h2[n]);
    }
#pragma unroll
    for (int n = 0; n < 32; n++) h2[n] = fmaxf(h2[n], 0.0f);

    float* orow = out + (size_t)r * 40;
#pragma unroll
    for (int n = 0; n < 40; n++) {
        float o = sb3[n];
#pragma unroll
        for (int k = 0; k < 32; k++)
            o = fmaf(h2[k], sW3[k * 40 + n], o);
        orow[n] = o;
    }
}

// ---------------- host launcher ---------------------------------------------
template<int OUTMODE, bool BIAS, bool RELU, bool AHALF>
static void launch_mma_gemm(const void* A, const float* W, const float* bias,
                            float* C, __half* C2, int M, int N, int K,
                            cudaStream_t st = 0) {
    cudaFuncSetAttribute(mma_gemm_kernel<OUTMODE, BIAS, RELU, AHALF>,
                         cudaFuncAttributeMaxDynamicSharedMemorySize, MMA_SMEM);
    dim3 grid((N + 127) / 128, (M + 127) / 128);
    mma_gemm_kernel<OUTMODE, BIAS, RELU, AHALF><<<grid, 256, MMA_SMEM, st>>>(A, W, bias, C, C2, M, N, K);
}

extern "C" void kernel_launch(void* const* d_in, const int* in_sizes, int n_in,
                              void* d_out, int out_size)
{
    const float* x      = (const float*)d_in[0];
    const int*   e_raw  = (const int*)d_in[1];
    const float* embW   = (const float*)d_in[2];
    const float* embB   = (const float*)d_in[3];
    const float* convW  = (const float*)d_in[4];
    const float* convB  = (const float*)d_in[5];
    const float* gamma  = (const float*)d_in[6];
    const float* beta   = (const float*)d_in[7];
    const float* W0 = (const float*)d_in[8];
    const float* b0 = (const float*)d_in[9];
    const float* W1 = (const float*)d_in[10];
    const float* b1 = (const float*)d_in[11];
    const float* W2 = (const float*)d_in[12];
    const float* b2 = (const float*)d_in[13];
    const float* W3 = (const float*)d_in[14];
    const float* b3 = (const float*)d_in[15];
    float* out = (float*)d_out;

    const int N = N_NODES;
    const int E = in_sizes[1] / 2;

    float *dinv, *selfw, *c2;
    __half *hw, *h16, *c1;
    int *src32, *dst32, *cnt, *ptr, *fill, *csr_src, *bsum;
    cudaGetSymbolAddress((void**)&h16,     g_h16);
    cudaGetSymbolAddress((void**)&hw,      g_hw);
    cudaGetSymbolAddress((void**)&dinv,    g_dinv);
    cudaGetSymbolAddress((void**)&selfw,   g_self);
    cudaGetSymbolAddress((void**)&c1,      g_c1);
    cudaGetSymbolAddress((void**)&c2,      g_c2);
    cudaGetSymbolAddress((void**)&src32,   g_src32);
    cudaGetSymbolAddress((void**)&dst32,   g_dst32);
    cudaGetSymbolAddress((void**)&cnt,     g_cnt);
    cudaGetSymbolAddress((void**)&ptr,     g_ptr);
    cudaGetSymbolAddress((void**)&fill,    g_fill);
    cudaGetSymbolAddress((void**)&csr_src, g_csr_src);
    cudaGetSymbolAddress((void**)&bsum,    g_bsum);

    int nb = (N + SCAN_B - 1) / SCAN_B;

    cudaStream_t s2;
    cudaEvent_t ev_fork, ev_prep;
    cudaStreamCreateWithFlags(&s2, cudaStreamNonBlocking);
    cudaEventCreateWithFlags(&ev_fork, cudaEventDisableTiming);
    cudaEventCreateWithFlags(&ev_prep, cudaEventDisableTiming);

    cudaEventRecord(ev_fork, 0);
    cudaStreamWaitEvent(s2, ev_fork, 0);

    // side stream: race-free, order-canonical CSR build
    zero_kernel<<<(N + 255) / 256, 256, 0, s2>>>(cnt, fill, N);   // happens-before atomics
    detect_kernel<<<1, 256, 0, s2>>>(e_raw, 1024);
    convert_count_kernel<<<(E + 255) / 256, 256, 0, s2>>>(e_raw, src32, dst32, cnt, E);
    norm_kernel<<<(N + 255) / 256, 256, 0, s2>>>(cnt, dinv, selfw, N);
    scan1_kernel<<<nb, SCAN_B, 0, s2>>>(cnt, ptr, bsum, N);
    scan2_kernel<<<1, 256, 0, s2>>>(bsum, nb);
    scan3_kernel<<<nb + 1, SCAN_B, 0, s2>>>(ptr, bsum, N, E);
    csr_fill_kernel<<<(E + 255) / 256, 256, 0, s2>>>(src32, dst32, ptr, fill, csr_src, E);
    sort_csr_kernel<<<(N + 255) / 256, 256, 0, s2>>>(ptr, csr_src, N);
    cudaEventRecord(ev_prep, s2);

    // main stream: embed GEMM (fp16 state) + conv1 GEMM
    launch_mma_gemm<1, true, false, false>(x, embW, embB, nullptr, h16, N, HID, 500);
    launch_mma_gemm<1, false, false, true>(h16, convW, nullptr, nullptr, hw, N, HID, HID);

    // join: aggregation needs the canonical CSR
    cudaStreamWaitEvent(0, ev_prep, 0);

    const int agg_blocks = (N + 7) / 8;
    for (int l = 0; l < 3; l++) {
        const float* cbl = convB + (size_t)l * HID;
        const float* gl  = gamma + (size_t)l * HID;
        const float* btl = beta  + (size_t)l * HID;

        agg_kernel<<<agg_blocks, 256>>>(ptr, csr_src, dinv, selfw, hw, cbl, gl, btl, h16, N);
        if (l + 1 < 3) {
            const float* Wn = convW + (size_t)(l + 1) * HID * HID;
            launch_mma_gemm<1, false, false, true>(h16, Wn, nullptr, nullptr, hw, N, HID, HID);
        }
    }

    // classifier MLP
    launch_mma_gemm<1, true, true, true>(h16, W0, b0, nullptr, c1, N, 128, 256);
    launch_mma_gemm<0, true, true, true>(c1, W1, b1, c2, nullptr, N, 64, 128);
    cls_tail_kernel<<<(N + 255) / 256, 256>>>(c2, W2, b2, W3, b3, out, N);
}